// round 1
// baseline (speedup 1.0000x reference)
#include <cuda_runtime.h>
#include <math.h>

// Problem constants (fixed by the reference setup_inputs)
#define NN    100000
#define EE    400000
#define BBG   4096
#define DD    256
#define MOLIN 25
#define FAB   100

// ---------------- device scratch (no allocations allowed) ----------------
__device__ float g_h[(size_t)NN * DD];     // post-lin0 node features
__device__ float g_agg[(size_t)NN * DD];   // message aggregation; becomes h2 after root
__device__ float g_e[NN];                  // attention scores
__device__ float g_hq[BBG * DD];           // LSTM hidden
__device__ float g_c[BBG * DD];            // LSTM cell
__device__ float g_q[BBG * 2 * DD];        // q_star = [hq, r]
__device__ float g_gates[BBG * 4 * DD];    // LSTM gates; reused as head hidden
__device__ int   g_counts[BBG];
__device__ int   g_segstart[BBG + 1];
__device__ int   g_is64;

__device__ __forceinline__ int ld_idx(const void* p, int i, int is64) {
    if (is64) return (int)((const long long*)p)[i];
    return ((const int*)p)[i];
}

__device__ __forceinline__ float sigf(float x) {
    return 1.0f / (1.0f + __expf(-x));
}

// ---------------- dtype detection: int64 vs int32 indices ----------------
// If edge_index is int64 with values in [0, N), every odd 32-bit word is 0.
// If int32, odd words are random indices (all-zero probability ~0).
__global__ void k_detect(const unsigned int* words) {
    __shared__ int nz;
    if (threadIdx.x == 0) nz = 0;
    __syncthreads();
    unsigned v = words[2 * threadIdx.x + 1];  // t in [0,512): words 1,3,...,1023
    if (v) atomicOr(&nz, 1);
    __syncthreads();
    if (threadIdx.x == 0) g_is64 = nz ? 0 : 1;
}

// ---------------- zero kernels ----------------
__global__ void k_zero_agg() {
    const int n = NN * DD;
    for (int i = blockIdx.x * blockDim.x + threadIdx.x; i < n; i += gridDim.x * blockDim.x)
        g_agg[i] = 0.0f;
}
__global__ void k_zero_state() {
    const int n = BBG * DD;
    for (int i = blockIdx.x * blockDim.x + threadIdx.x; i < n; i += gridDim.x * blockDim.x) {
        g_c[i] = 0.0f;
        if (i < BBG) g_counts[i] = 0;
    }
}

// ---------------- lin0: h = relu(x @ W0 + b0) ----------------
// 16 nodes per 256-thread block; each thread owns one output dim, W0 column in regs.
__global__ void k_lin0(const float* __restrict__ x, const float* __restrict__ W,
                       const float* __restrict__ b) {
    __shared__ float xs[16 * MOLIN];
    const int t = threadIdx.x;
    const int row0 = blockIdx.x * 16;
    for (int idx = t; idx < 16 * MOLIN; idx += 256)
        xs[idx] = x[row0 * MOLIN + idx];
    float w[MOLIN];
#pragma unroll
    for (int k = 0; k < MOLIN; k++) w[k] = W[k * DD + t];
    const float bd = b[t];
    __syncthreads();
#pragma unroll 4
    for (int i = 0; i < 16; i++) {
        float acc = bd;
#pragma unroll
        for (int k = 0; k < MOLIN; k++) acc += xs[i * MOLIN + k] * w[k];
        g_h[(size_t)(row0 + i) * DD + t] = fmaxf(acc, 0.0f);
    }
}

// ---------------- segment boundaries (batch is sorted) ----------------
__global__ void k_hist(const void* __restrict__ batch) {
    const int is64 = g_is64;
    for (int n = blockIdx.x * blockDim.x + threadIdx.x; n < NN; n += gridDim.x * blockDim.x) {
        int b = ld_idx(batch, n, is64);
        atomicAdd(&g_counts[b], 1);
    }
}

__global__ void k_scan() {  // 1 block, 1024 threads; exclusive scan of 4096 counts
    const int t = threadIdx.x;
    int c[4];
#pragma unroll
    for (int j = 0; j < 4; j++) c[j] = g_counts[t * 4 + j];
    int s = c[0] + c[1] + c[2] + c[3];
    const int lane = t & 31, wid = t >> 5;
    int inc = s;
#pragma unroll
    for (int o = 1; o < 32; o <<= 1) {
        int v = __shfl_up_sync(0xffffffffu, inc, o);
        if (lane >= o) inc += v;
    }
    __shared__ int wex[32];
    if (lane == 31) wex[wid] = inc;
    __syncthreads();
    if (wid == 0) {
        int v = wex[lane];
        int wi = v;
#pragma unroll
        for (int o = 1; o < 32; o <<= 1) {
            int u = __shfl_up_sync(0xffffffffu, wi, o);
            if (lane >= o) wi += u;
        }
        wex[lane] = wi - v;  // exclusive
    }
    __syncthreads();
    int run = wex[wid] + (inc - s);
#pragma unroll
    for (int j = 0; j < 4; j++) {
        g_segstart[t * 4 + j] = run;
        run += c[j];
    }
    if (t == 1023) g_segstart[BBG] = run;
}

// ---------------- fused edge kernel ----------------
// ew = edge_attr @ nn_w + nn_b ; msg = h[src]*ew ; agg[dst] += msg
// nn_w (100x256 = 100KB) fully resident in SMEM. 64 threads per edge,
// 4 dims per thread, 4 edges per block-iteration. Vector red.v4 scatter.
__global__ void k_edge(const void* __restrict__ eidx, const float* __restrict__ eattr,
                       const float* __restrict__ nnw, const float* __restrict__ nnb) {
    extern __shared__ float sm[];
    float* ws = sm;              // FAB*DD
    float* bs = ws + FAB * DD;   // DD
    float* as = bs + DD;         // 4*FAB
    const int t = threadIdx.x;
    const int is64 = g_is64;
    for (int idx = t; idx < FAB * DD; idx += 256) ws[idx] = nnw[idx];
    if (t < DD) bs[t] = nnb[t];
    const int g = t >> 6, l = t & 63, d0 = l * 4;
    const int nquad = (EE + 3) / 4;
    for (int q = blockIdx.x; q < nquad; q += gridDim.x) {
        const int e = q * 4 + g;
        __syncthreads();
        if (e < EE) {
            for (int j = l; j < FAB; j += 64) as[g * FAB + j] = eattr[(size_t)e * FAB + j];
        }
        __syncthreads();
        if (e < EE) {
            float4 acc = *(const float4*)(bs + d0);
            const float* ap = as + g * FAB;
#pragma unroll 4
            for (int k = 0; k < FAB; k++) {
                const float a = ap[k];
                const float4 wv = *(const float4*)(ws + k * DD + d0);
                acc.x += a * wv.x; acc.y += a * wv.y;
                acc.z += a * wv.z; acc.w += a * wv.w;
            }
            const int s  = ld_idx(eidx, e, is64);
            const int dn = ld_idx(eidx, EE + e, is64);
            const float4 hv = *(const float4*)&g_h[(size_t)s * DD + d0];
            const float mx = hv.x * acc.x, my = hv.y * acc.y;
            const float mz = hv.z * acc.z, mw = hv.w * acc.w;
            float* dst = &g_agg[(size_t)dn * DD + d0];
            asm volatile("red.global.add.v4.f32 [%0], {%1,%2,%3,%4};"
                         :: "l"(dst), "f"(mx), "f"(my), "f"(mz), "f"(mw) : "memory");
        }
    }
}

// ---------------- root GEMM: h2 = relu(h @ root_w + root_b + agg) -> g_agg ----------------
// 16 rows x 256 cols per block, K=256 tiled by 64; thread = 4x4 microtile.
__global__ void k_root(const float* __restrict__ W, const float* __restrict__ bias) {
    extern __shared__ float sm[];
    float* hs = sm;               // 16*256
    float* ws = sm + 16 * 256;    // 64*256
    const int t = threadIdx.x;
    const int row0 = blockIdx.x * 16;
    for (int idx = t; idx < 16 * 256; idx += 256)
        hs[idx] = g_h[(size_t)(row0 + (idx >> 8)) * DD + (idx & 255)];
    const int d0 = (t & 63) * 4, i0 = (t >> 6) * 4;
    float acc[4][4] = {};
    for (int kt = 0; kt < 4; kt++) {
        __syncthreads();
        for (int idx = t; idx < 64 * 256; idx += 256)
            ws[idx] = W[(size_t)(kt * 64 + (idx >> 8)) * DD + (idx & 255)];
        __syncthreads();
#pragma unroll
        for (int k = 0; k < 64; k++) {
            const float4 wv = *(const float4*)&ws[k * 256 + d0];
#pragma unroll
            for (int j = 0; j < 4; j++) {
                const float av = hs[(i0 + j) * 256 + kt * 64 + k];
                acc[j][0] += av * wv.x; acc[j][1] += av * wv.y;
                acc[j][2] += av * wv.z; acc[j][3] += av * wv.w;
            }
        }
    }
    const float4 bv = *(const float4*)&bias[d0];
#pragma unroll
    for (int j = 0; j < 4; j++) {
        const size_t base = (size_t)(row0 + i0 + j) * DD + d0;
        float4 ag = *(const float4*)&g_agg[base];
        float4 r;
        r.x = fmaxf(acc[j][0] + bv.x + ag.x, 0.0f);
        r.y = fmaxf(acc[j][1] + bv.y + ag.y, 0.0f);
        r.z = fmaxf(acc[j][2] + bv.z + ag.z, 0.0f);
        r.w = fmaxf(acc[j][3] + bv.w + ag.w, 0.0f);
        *(float4*)&g_agg[base] = r;
    }
}

// ---------------- LSTM gates GEMM: gates = q_star@Wih + hq@Whh + b ----------------
__global__ void k_lstm(const float* __restrict__ Wih, const float* __restrict__ Whh,
                       const float* __restrict__ bias) {
    extern __shared__ float sm[];
    float* aq = sm;                 // 16*512
    float* ah = sm + 8192;          // 16*256
    float* ws = sm + 12288;         // 64*256
    const int t = threadIdx.x;
    const int row0 = blockIdx.x * 16, col0 = blockIdx.y * 256;
    for (int idx = t; idx < 16 * 512; idx += 256)
        aq[idx] = g_q[(size_t)(row0 + (idx >> 9)) * 512 + (idx & 511)];
    for (int idx = t; idx < 16 * 256; idx += 256)
        ah[idx] = g_hq[(size_t)(row0 + (idx >> 8)) * 256 + (idx & 255)];
    const int d0 = (t & 63) * 4, i0 = (t >> 6) * 4;
    float acc[4][4] = {};
    for (int kt = 0; kt < 8; kt++) {  // Wih, K=512
        __syncthreads();
        for (int idx = t; idx < 64 * 256; idx += 256)
            ws[idx] = Wih[(size_t)(kt * 64 + (idx >> 8)) * 1024 + col0 + (idx & 255)];
        __syncthreads();
#pragma unroll
        for (int k = 0; k < 64; k++) {
            const float4 wv = *(const float4*)&ws[k * 256 + d0];
#pragma unroll
            for (int j = 0; j < 4; j++) {
                const float av = aq[(i0 + j) * 512 + kt * 64 + k];
                acc[j][0] += av * wv.x; acc[j][1] += av * wv.y;
                acc[j][2] += av * wv.z; acc[j][3] += av * wv.w;
            }
        }
    }
    for (int kt = 0; kt < 4; kt++) {  // Whh, K=256
        __syncthreads();
        for (int idx = t; idx < 64 * 256; idx += 256)
            ws[idx] = Whh[(size_t)(kt * 64 + (idx >> 8)) * 1024 + col0 + (idx & 255)];
        __syncthreads();
#pragma unroll
        for (int k = 0; k < 64; k++) {
            const float4 wv = *(const float4*)&ws[k * 256 + d0];
#pragma unroll
            for (int j = 0; j < 4; j++) {
                const float av = ah[(i0 + j) * 256 + kt * 64 + k];
                acc[j][0] += av * wv.x; acc[j][1] += av * wv.y;
                acc[j][2] += av * wv.z; acc[j][3] += av * wv.w;
            }
        }
    }
    const float4 bv = *(const float4*)&bias[col0 + d0];
#pragma unroll
    for (int j = 0; j < 4; j++) {
        float4 r;
        r.x = acc[j][0] + bv.x; r.y = acc[j][1] + bv.y;
        r.z = acc[j][2] + bv.z; r.w = acc[j][3] + bv.w;
        *(float4*)&g_gates[(size_t)(row0 + i0 + j) * 1024 + col0 + d0] = r;
    }
}

// ---------------- LSTM cell update ----------------
__global__ void k_cell(const float* __restrict__ bias, int useBias) {
    const int idx = blockIdx.x * blockDim.x + threadIdx.x;
    if (idx >= BBG * DD) return;
    const int b = idx >> 8, d = idx & 255;
    float gi, gf, gg, go;
    if (useBias) {  // step 0: q_star = hq = 0 algebraically => gates = bias
        gi = bias[d]; gf = bias[DD + d]; gg = bias[2 * DD + d]; go = bias[3 * DD + d];
    } else {
        const float* gp = g_gates + (size_t)b * 1024;
        gi = gp[d]; gf = gp[DD + d]; gg = gp[2 * DD + d]; go = gp[3 * DD + d];
    }
    const float c = sigf(gf) * g_c[idx] + sigf(gi) * tanhf(gg);
    g_c[idx] = c;
    const float hv = sigf(go) * tanhf(c);
    g_hq[idx] = hv;
    g_q[(size_t)b * 512 + d] = hv;
}

// ---------------- attention scores: e[n] = dot(h2[n], hq[batch[n]]) ----------------
__global__ void k_e(const void* __restrict__ batch) {
    const int t = threadIdx.x, wid = t >> 5, lane = t & 31;
    const int n = blockIdx.x * 8 + wid;
    if (n >= NN) return;
    const int is64 = g_is64;
    const int b = ld_idx(batch, n, is64);
    const float4* hp = (const float4*)(g_agg + (size_t)n * DD);
    const float4* qp = (const float4*)(g_hq + (size_t)b * DD);
    float s = 0.0f;
#pragma unroll
    for (int r = 0; r < 2; r++) {
        const float4 a = hp[lane + 32 * r];
        const float4 q = qp[lane + 32 * r];
        s += a.x * q.x + a.y * q.y + a.z * q.z + a.w * q.w;
    }
#pragma unroll
    for (int o = 16; o; o >>= 1) s += __shfl_xor_sync(0xffffffffu, s, o);
    if (lane == 0) g_e[n] = s;
}

// ---------------- segment softmax + weighted sum: r -> q_star[:,256:] ----------------
__global__ void k_attn() {  // one 128-thread block per graph; segments contiguous
    const int b = blockIdx.x, t = threadIdx.x;
    const int s0 = g_segstart[b], s1 = g_segstart[b + 1];
    __shared__ float sred[128];
    __shared__ float a_s[128];
    // pass 1: max
    float lm = -3.4e38f;
    for (int n = s0 + t; n < s1; n += 128) lm = fmaxf(lm, g_e[n]);
    sred[t] = lm;
    __syncthreads();
    for (int o = 64; o > 0; o >>= 1) {
        if (t < o) sred[t] = fmaxf(sred[t], sred[t + o]);
        __syncthreads();
    }
    const float m = (s1 > s0) ? sred[0] : 0.0f;
    __syncthreads();
    // pass 2: sum exp
    float lz = 0.0f;
    for (int n = s0 + t; n < s1; n += 128) lz += __expf(g_e[n] - m);
    sred[t] = lz;
    __syncthreads();
    for (int o = 64; o > 0; o >>= 1) {
        if (t < o) sred[t] += sred[t + o];
        __syncthreads();
    }
    const float z = sred[0];
    __syncthreads();
    // pass 3: r[d] = sum a*h2  (thread owns 2 dims)
    float rx = 0.0f, ry = 0.0f;
    for (int base = s0; base < s1; base += 128) {
        const int n = base + t;
        a_s[t] = (n < s1) ? __expf(g_e[n] - m) : 0.0f;
        __syncthreads();
        const int lim = min(128, s1 - base);
        for (int j = 0; j < lim; j++) {
            const float a = a_s[j];
            const float2 hv = *(const float2*)&g_agg[(size_t)(base + j) * DD + 2 * t];
            rx += a * hv.x;
            ry += a * hv.y;
        }
        __syncthreads();
    }
    const float inv = (s1 > s0) ? 1.0f / z : 0.0f;
    float2 out;
    out.x = rx * inv;
    out.y = ry * inv;
    *(float2*)&g_q[(size_t)b * 512 + 256 + 2 * t] = out;
}

// ---------------- head layer 1: hid = relu(q_star @ lin1_w + lin1_b) -> g_gates ----------------
__global__ void k_head1(const float* __restrict__ W, const float* __restrict__ bias) {
    extern __shared__ float sm[];
    float* aq = sm;             // 16*512
    float* ws = sm + 8192;      // 64*256
    const int t = threadIdx.x;
    const int row0 = blockIdx.x * 16;
    for (int idx = t; idx < 16 * 512; idx += 256)
        aq[idx] = g_q[(size_t)(row0 + (idx >> 9)) * 512 + (idx & 511)];
    const int d0 = (t & 63) * 4, i0 = (t >> 6) * 4;
    float acc[4][4] = {};
    for (int kt = 0; kt < 8; kt++) {
        __syncthreads();
        for (int idx = t; idx < 64 * 256; idx += 256)
            ws[idx] = W[(size_t)(kt * 64 + (idx >> 8)) * DD + (idx & 255)];
        __syncthreads();
#pragma unroll
        for (int k = 0; k < 64; k++) {
            const float4 wv = *(const float4*)&ws[k * 256 + d0];
#pragma unroll
            for (int j = 0; j < 4; j++) {
                const float av = aq[(i0 + j) * 512 + kt * 64 + k];
                acc[j][0] += av * wv.x; acc[j][1] += av * wv.y;
                acc[j][2] += av * wv.z; acc[j][3] += av * wv.w;
            }
        }
    }
    const float4 bv = *(const float4*)&bias[d0];
#pragma unroll
    for (int j = 0; j < 4; j++) {
        float4 r;
        r.x = fmaxf(acc[j][0] + bv.x, 0.0f);
        r.y = fmaxf(acc[j][1] + bv.y, 0.0f);
        r.z = fmaxf(acc[j][2] + bv.z, 0.0f);
        r.w = fmaxf(acc[j][3] + bv.w, 0.0f);
        *(float4*)&g_gates[(size_t)(row0 + i0 + j) * DD + d0] = r;
    }
}

// ---------------- head layer 2: out = hid @ lin2_w + lin2_b ----------------
__global__ void k_head2(const float* __restrict__ w2, const float* __restrict__ b2,
                        float* __restrict__ out) {
    const int t = threadIdx.x, wid = t >> 5, lane = t & 31;
    const int g = blockIdx.x * 8 + wid;
    if (g >= BBG) return;
    const float4* hp = (const float4*)(g_gates + (size_t)g * DD);
    const float4* wp = (const float4*)w2;
    float s = 0.0f;
#pragma unroll
    for (int r = 0; r < 2; r++) {
        const float4 a = hp[lane + 32 * r];
        const float4 w = wp[lane + 32 * r];
        s += a.x * w.x + a.y * w.y + a.z * w.z + a.w * w.w;
    }
#pragma unroll
    for (int o = 16; o; o >>= 1) s += __shfl_xor_sync(0xffffffffu, s, o);
    if (lane == 0) out[g] = s + b2[0];
}

// ---------------- host launch ----------------
extern "C" void kernel_launch(void* const* d_in, const int* in_sizes, int n_in,
                              void* d_out, int out_size) {
    const float* x      = (const float*)d_in[0];
    const void*  eidx   = d_in[1];
    const float* eattr  = (const float*)d_in[2];
    const void*  batch  = d_in[3];
    const float* lin0_w = (const float*)d_in[4];
    const float* lin0_b = (const float*)d_in[5];
    const float* root_w = (const float*)d_in[6];
    const float* root_b = (const float*)d_in[7];
    const float* nn_w   = (const float*)d_in[8];
    const float* nn_b   = (const float*)d_in[9];
    const float* wih    = (const float*)d_in[10];
    const float* whh    = (const float*)d_in[11];
    const float* lstm_b = (const float*)d_in[12];
    const float* lin1_w = (const float*)d_in[13];
    const float* lin1_b = (const float*)d_in[14];
    const float* lin2_w = (const float*)d_in[15];
    const float* lin2_b = (const float*)d_in[16];
    float* out = (float*)d_out;

    const int EDGE_SMEM = (FAB * DD + DD + 4 * FAB) * 4;            // 105024
    const int ROOT_SMEM = (16 * 256 + 64 * 256) * 4;                // 81920
    const int LSTM_SMEM = (16 * 512 + 16 * 256 + 64 * 256) * 4;     // 114688
    const int HEAD_SMEM = (16 * 512 + 64 * 256) * 4;                // 98304
    cudaFuncSetAttribute(k_edge,  cudaFuncAttributeMaxDynamicSharedMemorySize, EDGE_SMEM);
    cudaFuncSetAttribute(k_root,  cudaFuncAttributeMaxDynamicSharedMemorySize, ROOT_SMEM);
    cudaFuncSetAttribute(k_lstm,  cudaFuncAttributeMaxDynamicSharedMemorySize, LSTM_SMEM);
    cudaFuncSetAttribute(k_head1, cudaFuncAttributeMaxDynamicSharedMemorySize, HEAD_SMEM);

    k_detect<<<1, 512>>>((const unsigned int*)eidx);
    k_lin0<<<NN / 16, 256>>>(x, lin0_w, lin0_b);
    k_zero_agg<<<4096, 256>>>();
    k_zero_state<<<1024, 256>>>();
    k_hist<<<400, 256>>>(batch);
    k_scan<<<1, 1024>>>();
    k_edge<<<4096, 256, EDGE_SMEM>>>(eidx, eattr, nn_w, nn_b);
    k_root<<<NN / 16, 256, ROOT_SMEM>>>(root_w, root_b);

    for (int s = 0; s < 3; s++) {
        if (s == 0) {
            k_cell<<<BBG, 256>>>(lstm_b, 1);
        } else {
            k_lstm<<<dim3(BBG / 16, 4), 256, LSTM_SMEM>>>(wih, whh, lstm_b);
            k_cell<<<BBG, 256>>>(lstm_b, 0);
        }
        k_e<<<NN / 8, 256>>>(batch);
        k_attn<<<BBG, 128>>>();
    }

    k_head1<<<BBG / 16, 256, HEAD_SMEM>>>(lin1_w, lin1_b);
    k_head2<<<BBG / 8, 256>>>(lin2_w, lin2_b, out);
}

// round 2
// speedup vs baseline: 1.4191x; 1.4191x over previous
#include <cuda_runtime.h>
#include <math.h>

// Problem constants (fixed by the reference setup_inputs)
#define NN    100000
#define EE    400000
#define BBG   4096
#define DD    256
#define MOLIN 25
#define FAB   100

// ---------------- device scratch (no allocations allowed) ----------------
__device__ float g_h[(size_t)NN * DD];     // post-lin0 node features
__device__ float g_agg[(size_t)NN * DD];   // message aggregation; becomes h2 after root
__device__ float g_e[NN];                  // attention scores
__device__ float g_hq[BBG * DD];           // LSTM hidden
__device__ float g_c[BBG * DD];            // LSTM cell
__device__ float g_q[BBG * 2 * DD];        // q_star = [hq, r]
__device__ float g_gates[BBG * 4 * DD];    // LSTM gates; reused as head hidden
__device__ int   g_counts[BBG];
__device__ int   g_segstart[BBG + 1];
__device__ int   g_is64;

__device__ __forceinline__ int ld_idx(const void* p, int i, int is64) {
    if (is64) return (int)((const long long*)p)[i];
    return ((const int*)p)[i];
}

__device__ __forceinline__ float sigf(float x) {
    return 1.0f / (1.0f + __expf(-x));
}

// ---------------- dtype detection: int64 vs int32 indices ----------------
__global__ void k_detect(const unsigned int* words) {
    __shared__ int nz;
    if (threadIdx.x == 0) nz = 0;
    __syncthreads();
    unsigned v = words[2 * threadIdx.x + 1];
    if (v) atomicOr(&nz, 1);
    __syncthreads();
    if (threadIdx.x == 0) g_is64 = nz ? 0 : 1;
}

// ---------------- zero kernels ----------------
__global__ void k_zero_agg() {
    const int n = NN * DD;
    for (int i = blockIdx.x * blockDim.x + threadIdx.x; i < n; i += gridDim.x * blockDim.x)
        g_agg[i] = 0.0f;
}
__global__ void k_zero_state() {
    const int n = BBG * DD;
    for (int i = blockIdx.x * blockDim.x + threadIdx.x; i < n; i += gridDim.x * blockDim.x) {
        g_c[i] = 0.0f;
        if (i < BBG) g_counts[i] = 0;
    }
}

// ---------------- lin0: h = relu(x @ W0 + b0) ----------------
__global__ void k_lin0(const float* __restrict__ x, const float* __restrict__ W,
                       const float* __restrict__ b) {
    __shared__ float xs[16 * MOLIN];
    const int t = threadIdx.x;
    const int row0 = blockIdx.x * 16;
    for (int idx = t; idx < 16 * MOLIN; idx += 256)
        xs[idx] = x[row0 * MOLIN + idx];
    float w[MOLIN];
#pragma unroll
    for (int k = 0; k < MOLIN; k++) w[k] = W[k * DD + t];
    const float bd = b[t];
    __syncthreads();
#pragma unroll 4
    for (int i = 0; i < 16; i++) {
        float acc = bd;
#pragma unroll
        for (int k = 0; k < MOLIN; k++) acc += xs[i * MOLIN + k] * w[k];
        g_h[(size_t)(row0 + i) * DD + t] = fmaxf(acc, 0.0f);
    }
}

// ---------------- segment boundaries (batch is sorted) ----------------
__global__ void k_hist(const void* __restrict__ batch) {
    const int is64 = g_is64;
    for (int n = blockIdx.x * blockDim.x + threadIdx.x; n < NN; n += gridDim.x * blockDim.x) {
        int b = ld_idx(batch, n, is64);
        atomicAdd(&g_counts[b], 1);
    }
}

__global__ void k_scan() {  // 1 block, 1024 threads; exclusive scan of 4096 counts
    const int t = threadIdx.x;
    int c[4];
#pragma unroll
    for (int j = 0; j < 4; j++) c[j] = g_counts[t * 4 + j];
    int s = c[0] + c[1] + c[2] + c[3];
    const int lane = t & 31, wid = t >> 5;
    int inc = s;
#pragma unroll
    for (int o = 1; o < 32; o <<= 1) {
        int v = __shfl_up_sync(0xffffffffu, inc, o);
        if (lane >= o) inc += v;
    }
    __shared__ int wex[32];
    if (lane == 31) wex[wid] = inc;
    __syncthreads();
    if (wid == 0) {
        int v = wex[lane];
        int wi = v;
#pragma unroll
        for (int o = 1; o < 32; o <<= 1) {
            int u = __shfl_up_sync(0xffffffffu, wi, o);
            if (lane >= o) wi += u;
        }
        wex[lane] = wi - v;  // exclusive
    }
    __syncthreads();
    int run = wex[wid] + (inc - s);
#pragma unroll
    for (int j = 0; j < 4; j++) {
        g_segstart[t * 4 + j] = run;
        run += c[j];
    }
    if (t == 1023) g_segstart[BBG] = run;
}

// ---------------- fused edge kernel (8 edges/thread-group, double-buffered) ----------------
// ew = edge_attr @ nn_w + nn_b ; msg = h[src]*ew ; agg[dst] += msg
// nn_w (100x256 = 100KB) resident in SMEM. 64 threads x 4 dims; each 64-thread
// group owns 8 edges -> one weight float4 LDS feeds 32 FFMA. Attr chunks
// (32 edges, contiguous 12.8KB) double-buffered: LDG at loop top, STS after
// compute, one __syncthreads per chunk.
#define ECHUNK 32                          // edges per block-iteration (EE % 32 == 0)
#define EFLOAT (ECHUNK * FAB)              // 3200 floats per chunk
#define EVEC   (EFLOAT / 4)                // 800 float4 per chunk
__global__ void __launch_bounds__(256, 1)
k_edge(const void* __restrict__ eidx, const float* __restrict__ eattr,
       const float* __restrict__ nnw, const float* __restrict__ nnb) {
    extern __shared__ float sm[];
    float* ws = sm;                        // FAB*DD = 25600 floats
    float* bs = ws + FAB * DD;             // DD
    float* as = bs + DD;                   // 2 * EFLOAT (double buffer)
    const int t = threadIdx.x;
    const int is64 = g_is64;

    const int NCH = EE / ECHUNK;           // 12500
    const int per = (NCH + gridDim.x - 1) / gridDim.x;
    const int c0 = blockIdx.x * per;
    const int c1 = min(NCH, c0 + per);
    if (c0 >= c1) return;

    for (int idx = t; idx < FAB * DD; idx += 256) ws[idx] = nnw[idx];
    if (t < DD) bs[t] = nnb[t];

    const int g = t >> 6, l = t & 63, d0 = l * 4;
    const float4* ea = (const float4*)eattr;

    // preload first chunk into buffer 0
    for (int idx = t; idx < EVEC; idx += 256)
        ((float4*)as)[idx] = ea[(size_t)c0 * EVEC + idx];
    __syncthreads();

    int buf = 0;
    for (int c = c0; c < c1; ++c) {
        // prefetch next chunk into registers (latency hidden by compute)
        float4 pre[4];
        int np = 0;
        if (c + 1 < c1) {
            for (int idx = t; idx < EVEC; idx += 256, np++)
                pre[np] = ea[(size_t)(c + 1) * EVEC + idx];
        }

        // compute ew for 8 edges x 4 dims
        const float4 bv = *(const float4*)(bs + d0);
        float4 acc[8];
#pragma unroll
        for (int j = 0; j < 8; j++) acc[j] = bv;
        const float* ap = as + buf * EFLOAT + (g * 8) * FAB;
#pragma unroll 2
        for (int k = 0; k < FAB; k++) {
            const float4 wv = *(const float4*)(ws + k * DD + d0);
#pragma unroll
            for (int j = 0; j < 8; j++) {
                const float a = ap[j * FAB + k];  // warp-uniform -> broadcast
                acc[j].x += a * wv.x; acc[j].y += a * wv.y;
                acc[j].z += a * wv.z; acc[j].w += a * wv.w;
            }
        }

        // gather h[src], modulate, scatter-add to agg[dst]
        const int ebase = c * ECHUNK + g * 8;
#pragma unroll
        for (int j = 0; j < 8; j++) {
            const int e  = ebase + j;
            const int s  = ld_idx(eidx, e, is64);
            const int dn = ld_idx(eidx, EE + e, is64);
            const float4 hv = *(const float4*)&g_h[(size_t)s * DD + d0];
            const float mx = hv.x * acc[j].x, my = hv.y * acc[j].y;
            const float mz = hv.z * acc[j].z, mw = hv.w * acc[j].w;
            float* dst = &g_agg[(size_t)dn * DD + d0];
            asm volatile("red.global.add.v4.f32 [%0], {%1,%2,%3,%4};"
                         :: "l"(dst), "f"(mx), "f"(my), "f"(mz), "f"(mw) : "memory");
        }

        // commit prefetched chunk to the other buffer
        if (c + 1 < c1) {
            float4* dstb = (float4*)(as + (buf ^ 1) * EFLOAT);
            np = 0;
            for (int idx = t; idx < EVEC; idx += 256, np++)
                dstb[idx] = pre[np];
        }
        __syncthreads();
        buf ^= 1;
    }
}

// ---------------- root GEMM: h2 = relu(h @ root_w + root_b + agg) -> g_agg ----------------
// 32 rows x 256 cols per block, K tiled by 64; thread = 8x4 microtile.
__global__ void __launch_bounds__(256, 1)
k_root(const float* __restrict__ W, const float* __restrict__ bias) {
    extern __shared__ float sm[];
    float* hs = sm;               // 32*256 floats = 32KB
    float* ws = sm + 32 * 256;    // 64*256 floats = 64KB
    const int t = threadIdx.x;
    const int row0 = blockIdx.x * 32;
    for (int idx = t; idx < 32 * 256; idx += 256)
        hs[idx] = g_h[(size_t)(row0 + (idx >> 8)) * DD + (idx & 255)];
    const int d0 = (t & 63) * 4, i0 = (t >> 6) * 8;
    float acc[8][4] = {};
    for (int kt = 0; kt < 4; kt++) {
        __syncthreads();
        for (int idx = t; idx < 64 * 256; idx += 256)
            ws[idx] = W[(size_t)(kt * 64 + (idx >> 8)) * DD + (idx & 255)];
        __syncthreads();
#pragma unroll 2
        for (int k = 0; k < 64; k++) {
            const float4 wv = *(const float4*)&ws[k * 256 + d0];
#pragma unroll
            for (int j = 0; j < 8; j++) {
                const float av = hs[(i0 + j) * 256 + kt * 64 + k];  // broadcast
                acc[j][0] += av * wv.x; acc[j][1] += av * wv.y;
                acc[j][2] += av * wv.z; acc[j][3] += av * wv.w;
            }
        }
    }
    const float4 bv = *(const float4*)&bias[d0];
#pragma unroll
    for (int j = 0; j < 8; j++) {
        const size_t base = (size_t)(row0 + i0 + j) * DD + d0;
        float4 ag = *(const float4*)&g_agg[base];
        float4 r;
        r.x = fmaxf(acc[j][0] + bv.x + ag.x, 0.0f);
        r.y = fmaxf(acc[j][1] + bv.y + ag.y, 0.0f);
        r.z = fmaxf(acc[j][2] + bv.z + ag.z, 0.0f);
        r.w = fmaxf(acc[j][3] + bv.w + ag.w, 0.0f);
        *(float4*)&g_agg[base] = r;
    }
}

// ---------------- LSTM gates GEMM: gates = q_star@Wih + hq@Whh + b ----------------
__global__ void k_lstm(const float* __restrict__ Wih, const float* __restrict__ Whh,
                       const float* __restrict__ bias) {
    extern __shared__ float sm[];
    float* aq = sm;                 // 16*512
    float* ah = sm + 8192;          // 16*256
    float* ws = sm + 12288;         // 64*256
    const int t = threadIdx.x;
    const int row0 = blockIdx.x * 16, col0 = blockIdx.y * 256;
    for (int idx = t; idx < 16 * 512; idx += 256)
        aq[idx] = g_q[(size_t)(row0 + (idx >> 9)) * 512 + (idx & 511)];
    for (int idx = t; idx < 16 * 256; idx += 256)
        ah[idx] = g_hq[(size_t)(row0 + (idx >> 8)) * 256 + (idx & 255)];
    const int d0 = (t & 63) * 4, i0 = (t >> 6) * 4;
    float acc[4][4] = {};
    for (int kt = 0; kt < 8; kt++) {  // Wih, K=512
        __syncthreads();
        for (int idx = t; idx < 64 * 256; idx += 256)
            ws[idx] = Wih[(size_t)(kt * 64 + (idx >> 8)) * 1024 + col0 + (idx & 255)];
        __syncthreads();
#pragma unroll
        for (int k = 0; k < 64; k++) {
            const float4 wv = *(const float4*)&ws[k * 256 + d0];
#pragma unroll
            for (int j = 0; j < 4; j++) {
                const float av = aq[(i0 + j) * 512 + kt * 64 + k];
                acc[j][0] += av * wv.x; acc[j][1] += av * wv.y;
                acc[j][2] += av * wv.z; acc[j][3] += av * wv.w;
            }
        }
    }
    for (int kt = 0; kt < 4; kt++) {  // Whh, K=256
        __syncthreads();
        for (int idx = t; idx < 64 * 256; idx += 256)
            ws[idx] = Whh[(size_t)(kt * 64 + (idx >> 8)) * 1024 + col0 + (idx & 255)];
        __syncthreads();
#pragma unroll
        for (int k = 0; k < 64; k++) {
            const float4 wv = *(const float4*)&ws[k * 256 + d0];
#pragma unroll
            for (int j = 0; j < 4; j++) {
                const float av = ah[(i0 + j) * 256 + kt * 64 + k];
                acc[j][0] += av * wv.x; acc[j][1] += av * wv.y;
                acc[j][2] += av * wv.z; acc[j][3] += av * wv.w;
            }
        }
    }
    const float4 bv = *(const float4*)&bias[col0 + d0];
#pragma unroll
    for (int j = 0; j < 4; j++) {
        float4 r;
        r.x = acc[j][0] + bv.x; r.y = acc[j][1] + bv.y;
        r.z = acc[j][2] + bv.z; r.w = acc[j][3] + bv.w;
        *(float4*)&g_gates[(size_t)(row0 + i0 + j) * 1024 + col0 + d0] = r;
    }
}

// ---------------- LSTM cell update ----------------
__global__ void k_cell(const float* __restrict__ bias, int useBias) {
    const int idx = blockIdx.x * blockDim.x + threadIdx.x;
    if (idx >= BBG * DD) return;
    const int b = idx >> 8, d = idx & 255;
    float gi, gf, gg, go;
    if (useBias) {  // step 0: q_star = hq = 0 algebraically => gates = bias
        gi = bias[d]; gf = bias[DD + d]; gg = bias[2 * DD + d]; go = bias[3 * DD + d];
    } else {
        const float* gp = g_gates + (size_t)b * 1024;
        gi = gp[d]; gf = gp[DD + d]; gg = gp[2 * DD + d]; go = gp[3 * DD + d];
    }
    const float c = sigf(gf) * g_c[idx] + sigf(gi) * tanhf(gg);
    g_c[idx] = c;
    const float hv = sigf(go) * tanhf(c);
    g_hq[idx] = hv;
    g_q[(size_t)b * 512 + d] = hv;
}

// ---------------- attention scores: e[n] = dot(h2[n], hq[batch[n]]) ----------------
__global__ void k_e(const void* __restrict__ batch) {
    const int t = threadIdx.x, wid = t >> 5, lane = t & 31;
    const int n = blockIdx.x * 8 + wid;
    if (n >= NN) return;
    const int is64 = g_is64;
    const int b = ld_idx(batch, n, is64);
    const float4* hp = (const float4*)(g_agg + (size_t)n * DD);
    const float4* qp = (const float4*)(g_hq + (size_t)b * DD);
    float s = 0.0f;
#pragma unroll
    for (int r = 0; r < 2; r++) {
        const float4 a = hp[lane + 32 * r];
        const float4 q = qp[lane + 32 * r];
        s += a.x * q.x + a.y * q.y + a.z * q.z + a.w * q.w;
    }
#pragma unroll
    for (int o = 16; o; o >>= 1) s += __shfl_xor_sync(0xffffffffu, s, o);
    if (lane == 0) g_e[n] = s;
}

// ---------------- segment softmax + weighted sum: r -> q_star[:,256:] ----------------
__global__ void k_attn() {  // one 128-thread block per graph; segments contiguous
    const int b = blockIdx.x, t = threadIdx.x;
    const int s0 = g_segstart[b], s1 = g_segstart[b + 1];
    __shared__ float sred[128];
    __shared__ float a_s[128];
    float lm = -3.4e38f;
    for (int n = s0 + t; n < s1; n += 128) lm = fmaxf(lm, g_e[n]);
    sred[t] = lm;
    __syncthreads();
    for (int o = 64; o > 0; o >>= 1) {
        if (t < o) sred[t] = fmaxf(sred[t], sred[t + o]);
        __syncthreads();
    }
    const float m = (s1 > s0) ? sred[0] : 0.0f;
    __syncthreads();
    float lz = 0.0f;
    for (int n = s0 + t; n < s1; n += 128) lz += __expf(g_e[n] - m);
    sred[t] = lz;
    __syncthreads();
    for (int o = 64; o > 0; o >>= 1) {
        if (t < o) sred[t] += sred[t + o];
        __syncthreads();
    }
    const float z = sred[0];
    __syncthreads();
    float rx = 0.0f, ry = 0.0f;
    for (int base = s0; base < s1; base += 128) {
        const int n = base + t;
        a_s[t] = (n < s1) ? __expf(g_e[n] - m) : 0.0f;
        __syncthreads();
        const int lim = min(128, s1 - base);
        for (int j = 0; j < lim; j++) {
            const float a = a_s[j];
            const float2 hv = *(const float2*)&g_agg[(size_t)(base + j) * DD + 2 * t];
            rx += a * hv.x;
            ry += a * hv.y;
        }
        __syncthreads();
    }
    const float inv = (s1 > s0) ? 1.0f / z : 0.0f;
    float2 out;
    out.x = rx * inv;
    out.y = ry * inv;
    *(float2*)&g_q[(size_t)b * 512 + 256 + 2 * t] = out;
}

// ---------------- head layer 1: hid = relu(q_star @ lin1_w + lin1_b) -> g_gates ----------------
__global__ void k_head1(const float* __restrict__ W, const float* __restrict__ bias) {
    extern __shared__ float sm[];
    float* aq = sm;             // 16*512
    float* ws = sm + 8192;      // 64*256
    const int t = threadIdx.x;
    const int row0 = blockIdx.x * 16;
    for (int idx = t; idx < 16 * 512; idx += 256)
        aq[idx] = g_q[(size_t)(row0 + (idx >> 9)) * 512 + (idx & 511)];
    const int d0 = (t & 63) * 4, i0 = (t >> 6) * 4;
    float acc[4][4] = {};
    for (int kt = 0; kt < 8; kt++) {
        __syncthreads();
        for (int idx = t; idx < 64 * 256; idx += 256)
            ws[idx] = W[(size_t)(kt * 64 + (idx >> 8)) * DD + (idx & 255)];
        __syncthreads();
#pragma unroll
        for (int k = 0; k < 64; k++) {
            const float4 wv = *(const float4*)&ws[k * 256 + d0];
#pragma unroll
            for (int j = 0; j < 4; j++) {
                const float av = aq[(i0 + j) * 512 + kt * 64 + k];
                acc[j][0] += av * wv.x; acc[j][1] += av * wv.y;
                acc[j][2] += av * wv.z; acc[j][3] += av * wv.w;
            }
        }
    }
    const float4 bv = *(const float4*)&bias[d0];
#pragma unroll
    for (int j = 0; j < 4; j++) {
        float4 r;
        r.x = fmaxf(acc[j][0] + bv.x, 0.0f);
        r.y = fmaxf(acc[j][1] + bv.y, 0.0f);
        r.z = fmaxf(acc[j][2] + bv.z, 0.0f);
        r.w = fmaxf(acc[j][3] + bv.w, 0.0f);
        *(float4*)&g_gates[(size_t)(row0 + i0 + j) * DD + d0] = r;
    }
}

// ---------------- head layer 2: out = hid @ lin2_w + lin2_b ----------------
__global__ void k_head2(const float* __restrict__ w2, const float* __restrict__ b2,
                        float* __restrict__ out) {
    const int t = threadIdx.x, wid = t >> 5, lane = t & 31;
    const int g = blockIdx.x * 8 + wid;
    if (g >= BBG) return;
    const float4* hp = (const float4*)(g_gates + (size_t)g * DD);
    const float4* wp = (const float4*)w2;
    float s = 0.0f;
#pragma unroll
    for (int r = 0; r < 2; r++) {
        const float4 a = hp[lane + 32 * r];
        const float4 w = wp[lane + 32 * r];
        s += a.x * w.x + a.y * w.y + a.z * w.z + a.w * w.w;
    }
#pragma unroll
    for (int o = 16; o; o >>= 1) s += __shfl_xor_sync(0xffffffffu, s, o);
    if (lane == 0) out[g] = s + b2[0];
}

// ---------------- host launch ----------------
extern "C" void kernel_launch(void* const* d_in, const int* in_sizes, int n_in,
                              void* d_out, int out_size) {
    const float* x      = (const float*)d_in[0];
    const void*  eidx   = d_in[1];
    const float* eattr  = (const float*)d_in[2];
    const void*  batch  = d_in[3];
    const float* lin0_w = (const float*)d_in[4];
    const float* lin0_b = (const float*)d_in[5];
    const float* root_w = (const float*)d_in[6];
    const float* root_b = (const float*)d_in[7];
    const float* nn_w   = (const float*)d_in[8];
    const float* nn_b   = (const float*)d_in[9];
    const float* wih    = (const float*)d_in[10];
    const float* whh    = (const float*)d_in[11];
    const float* lstm_b = (const float*)d_in[12];
    const float* lin1_w = (const float*)d_in[13];
    const float* lin1_b = (const float*)d_in[14];
    const float* lin2_w = (const float*)d_in[15];
    const float* lin2_b = (const float*)d_in[16];
    float* out = (float*)d_out;

    const int EDGE_SMEM = (FAB * DD + DD + 2 * EFLOAT) * 4;         // 129024
    const int ROOT_SMEM = (32 * 256 + 64 * 256) * 4;                // 98304
    const int LSTM_SMEM = (16 * 512 + 16 * 256 + 64 * 256) * 4;     // 114688
    const int HEAD_SMEM = (16 * 512 + 64 * 256) * 4;                // 98304
    cudaFuncSetAttribute(k_edge,  cudaFuncAttributeMaxDynamicSharedMemorySize, EDGE_SMEM);
    cudaFuncSetAttribute(k_root,  cudaFuncAttributeMaxDynamicSharedMemorySize, ROOT_SMEM);
    cudaFuncSetAttribute(k_lstm,  cudaFuncAttributeMaxDynamicSharedMemorySize, LSTM_SMEM);
    cudaFuncSetAttribute(k_head1, cudaFuncAttributeMaxDynamicSharedMemorySize, HEAD_SMEM);

    k_detect<<<1, 512>>>((const unsigned int*)eidx);
    k_lin0<<<NN / 16, 256>>>(x, lin0_w, lin0_b);
    k_zero_agg<<<4096, 256>>>();
    k_zero_state<<<1024, 256>>>();
    k_hist<<<400, 256>>>(batch);
    k_scan<<<1, 1024>>>();
    k_edge<<<148, 256, EDGE_SMEM>>>(eidx, eattr, nn_w, nn_b);
    k_root<<<NN / 32, 256, ROOT_SMEM>>>(root_w, root_b);

    for (int s = 0; s < 3; s++) {
        if (s == 0) {
            k_cell<<<BBG, 256>>>(lstm_b, 1);
        } else {
            k_lstm<<<dim3(BBG / 16, 4), 256, LSTM_SMEM>>>(wih, whh, lstm_b);
            k_cell<<<BBG, 256>>>(lstm_b, 0);
        }
        k_e<<<NN / 8, 256>>>(batch);
        k_attn<<<BBG, 128>>>();
    }

    k_head1<<<BBG / 16, 256, HEAD_SMEM>>>(lin1_w, lin1_b);
    k_head2<<<BBG / 8, 256>>>(lin2_w, lin2_b, out);
}

// round 4
// speedup vs baseline: 1.6073x; 1.1326x over previous
#include <cuda_runtime.h>
#include <math.h>
#include <stdint.h>

// Problem constants (fixed by the reference setup_inputs)
#define NN    100000
#define EE    400000
#define BBG   4096
#define DD    256
#define MOLIN 25
#define FAB   100

// ---------------- device scratch (no allocations allowed) ----------------
__device__ float g_h[(size_t)NN * DD];     // post-lin0 node features
__device__ float g_agg[(size_t)NN * DD];   // message aggregation; becomes h2 after root
__device__ float g_e[NN];                  // attention scores
__device__ float g_hq[BBG * DD];           // LSTM hidden
__device__ float g_c[BBG * DD];            // LSTM cell
__device__ float g_q[BBG * 2 * DD];        // q_star = [hq, r]
__device__ float g_gates[BBG * 4 * DD];    // LSTM gates; reused as head hidden
__device__ int   g_counts[BBG];
__device__ int   g_segstart[BBG + 1];
__device__ int   g_is64;

__device__ __forceinline__ int ld_idx(const void* p, int i, int is64) {
    if (is64) return (int)((const long long*)p)[i];
    return ((const int*)p)[i];
}

__device__ __forceinline__ float sigf(float x) {
    return 1.0f / (1.0f + __expf(-x));
}

// tf32 conversion: destination must be a .b32 register for ptxas
__device__ __forceinline__ float to_tf32(float v) {
    uint32_t o;
    asm("cvt.rna.tf32.f32 %0, %1;" : "=r"(o) : "f"(v));
    return __uint_as_float(o);
}

// ---------------- dtype detection: int64 vs int32 indices ----------------
__global__ void k_detect(const unsigned int* words) {
    __shared__ int nz;
    if (threadIdx.x == 0) nz = 0;
    __syncthreads();
    unsigned v = words[2 * threadIdx.x + 1];
    if (v) atomicOr(&nz, 1);
    __syncthreads();
    if (threadIdx.x == 0) g_is64 = nz ? 0 : 1;
}

// ---------------- zero kernels ----------------
__global__ void k_zero_agg() {
    const int n = NN * DD;
    for (int i = blockIdx.x * blockDim.x + threadIdx.x; i < n; i += gridDim.x * blockDim.x)
        g_agg[i] = 0.0f;
}
__global__ void k_zero_state() {
    const int n = BBG * DD;
    for (int i = blockIdx.x * blockDim.x + threadIdx.x; i < n; i += gridDim.x * blockDim.x) {
        g_c[i] = 0.0f;
        if (i < BBG) g_counts[i] = 0;
    }
}

// ---------------- lin0: h = relu(x @ W0 + b0) ----------------
__global__ void k_lin0(const float* __restrict__ x, const float* __restrict__ W,
                       const float* __restrict__ b) {
    __shared__ float xs[16 * MOLIN];
    const int t = threadIdx.x;
    const int row0 = blockIdx.x * 16;
    for (int idx = t; idx < 16 * MOLIN; idx += 256)
        xs[idx] = x[row0 * MOLIN + idx];
    float w[MOLIN];
#pragma unroll
    for (int k = 0; k < MOLIN; k++) w[k] = W[k * DD + t];
    const float bd = b[t];
    __syncthreads();
#pragma unroll 4
    for (int i = 0; i < 16; i++) {
        float acc = bd;
#pragma unroll
        for (int k = 0; k < MOLIN; k++) acc += xs[i * MOLIN + k] * w[k];
        g_h[(size_t)(row0 + i) * DD + t] = fmaxf(acc, 0.0f);
    }
}

// ---------------- segment boundaries (batch is sorted) ----------------
__global__ void k_hist(const void* __restrict__ batch) {
    const int is64 = g_is64;
    for (int n = blockIdx.x * blockDim.x + threadIdx.x; n < NN; n += gridDim.x * blockDim.x) {
        int b = ld_idx(batch, n, is64);
        atomicAdd(&g_counts[b], 1);
    }
}

__global__ void k_scan() {  // 1 block, 1024 threads; exclusive scan of 4096 counts
    const int t = threadIdx.x;
    int c[4];
#pragma unroll
    for (int j = 0; j < 4; j++) c[j] = g_counts[t * 4 + j];
    int s = c[0] + c[1] + c[2] + c[3];
    const int lane = t & 31, wid = t >> 5;
    int inc = s;
#pragma unroll
    for (int o = 1; o < 32; o <<= 1) {
        int v = __shfl_up_sync(0xffffffffu, inc, o);
        if (lane >= o) inc += v;
    }
    __shared__ int wex[32];
    if (lane == 31) wex[wid] = inc;
    __syncthreads();
    if (wid == 0) {
        int v = wex[lane];
        int wi = v;
#pragma unroll
        for (int o = 1; o < 32; o <<= 1) {
            int u = __shfl_up_sync(0xffffffffu, wi, o);
            if (lane >= o) wi += u;
        }
        wex[lane] = wi - v;  // exclusive
    }
    __syncthreads();
    int run = wex[wid] + (inc - s);
#pragma unroll
    for (int j = 0; j < 4; j++) {
        g_segstart[t * 4 + j] = run;
        run += c[j];
    }
    if (t == 1023) g_segstart[BBG] = run;
}

// ---------------- fused edge kernel: tf32 mma.sync ----------------
// ew = [eattr | 1] @ [nn_w ; nn_b]  (bias folded as K-row 100; K padded to 104)
// msg = h[src] * ew ; agg[dst] += msg (red.global.add.v2.f32)
// Warp tile: 16 edges x 64 dims via m16n8k8 (8 n-tiles x 13 k-steps).
#define ECH   32
#define EVEC  (ECH * FAB / 4)   // 800 float4 per chunk
#define KPAD  104
#define A_STR 108
#define B_STR 264
__global__ void __launch_bounds__(256, 1)
k_edge(const void* __restrict__ eidx, const float* __restrict__ eattr,
       const float* __restrict__ nnw, const float* __restrict__ nnb) {
    extern __shared__ float sm[];
    float* ws = sm;                      // KPAD * B_STR = 27456 floats
    float* as = ws + KPAD * B_STR;       // 2 * ECH * A_STR = 6912 floats
    const int t = threadIdx.x;
    const int is64 = g_is64;

    // weights (+bias row 100, zero rows 101-103), tf32-converted
    for (int idx = t; idx < KPAD * 256; idx += 256) {
        const int r = idx >> 8, cc = idx & 255;
        float v = (r < FAB) ? nnw[r * 256 + cc] : (r == FAB ? nnb[cc] : 0.0f);
        ws[r * B_STR + cc] = to_tf32(v);
    }
    // attr pad columns (both buffers): col 100 = 1.0 (bias), 101..107 = 0
    for (int idx = t; idx < 2 * ECH; idx += 256) {
        float* row = as + idx * A_STR;
#pragma unroll
        for (int j = 100; j < 108; j++) row[j] = 0.0f;
        row[100] = 1.0f;
    }

    const int NCH = EE / ECH;            // 12500
    const int per = (NCH + gridDim.x - 1) / gridDim.x;
    const int cs = blockIdx.x * per;
    const int ce = min(NCH, cs + per);
    if (cs >= ce) return;

    const float4* ea = (const float4*)eattr;
    // preload first chunk into buffer 0
    for (int idx = t; idx < EVEC; idx += 256) {
        float4 v = ea[(size_t)cs * EVEC + idx];
        const int f0 = idx * 4;
        const int e = f0 / FAB, col = f0 % FAB;
        float4 o;
        o.x = to_tf32(v.x); o.y = to_tf32(v.y);
        o.z = to_tf32(v.z); o.w = to_tf32(v.w);
        *(float4*)(as + e * A_STR + col) = o;
    }
    __syncthreads();

    const int w = t >> 5, lane = t & 31;
    const int eg = w >> 2, ng = w & 3;       // edge group (0/1), dim group (0..3)
    const int qr = lane >> 2, rr = lane & 3; // quad-row, quad-col

    int buf = 0;
    for (int c = cs; c < ce; ++c) {
        // prefetch next chunk (raw) into registers
        float4 pre[4];
        int np = 0;
        if (c + 1 < ce) {
            for (int idx = t; idx < EVEC; idx += 256, np++)
                pre[np] = ea[(size_t)(c + 1) * EVEC + idx];
        }

        // ---- MMA: C[16 edges x 64 dims] ----
        float acc[8][4];
#pragma unroll
        for (int nt = 0; nt < 8; nt++)
#pragma unroll
            for (int j = 0; j < 4; j++) acc[nt][j] = 0.0f;

        const float* A = as + buf * ECH * A_STR + (eg * 16 + qr) * A_STR;
#pragma unroll
        for (int ks = 0; ks < 13; ks++) {
            const int k0 = ks * 8;
            const uint32_t a0 = __float_as_uint(A[k0 + rr]);
            const uint32_t a1 = __float_as_uint(A[8 * A_STR + k0 + rr]);
            const uint32_t a2 = __float_as_uint(A[k0 + rr + 4]);
            const uint32_t a3 = __float_as_uint(A[8 * A_STR + k0 + rr + 4]);
            const float* Bp = ws + (k0 + rr) * B_STR + ng * 64 + qr;
#pragma unroll
            for (int nt = 0; nt < 8; nt++) {
                const uint32_t b0 = __float_as_uint(Bp[nt * 8]);
                const uint32_t b1 = __float_as_uint(Bp[4 * B_STR + nt * 8]);
                asm volatile(
                    "mma.sync.aligned.m16n8k8.row.col.f32.tf32.tf32.f32 "
                    "{%0,%1,%2,%3}, {%4,%5,%6,%7}, {%8,%9}, {%0,%1,%2,%3};"
                    : "+f"(acc[nt][0]), "+f"(acc[nt][1]),
                      "+f"(acc[nt][2]), "+f"(acc[nt][3])
                    : "r"(a0), "r"(a1), "r"(a2), "r"(a3), "r"(b0), "r"(b1));
            }
        }

        // ---- epilogue: gather h[src], modulate, scatter to agg[dst] ----
        const int ebase = c * ECH + eg * 16;
        const int e0 = ebase + qr, e1 = ebase + qr + 8;
        const int s0 = ld_idx(eidx, e0, is64), d0 = ld_idx(eidx, EE + e0, is64);
        const int s1 = ld_idx(eidx, e1, is64), d1 = ld_idx(eidx, EE + e1, is64);
        const float* h0 = g_h + (size_t)s0 * DD;
        const float* h1 = g_h + (size_t)s1 * DD;
        float* a0p = g_agg + (size_t)d0 * DD;
        float* a1p = g_agg + (size_t)d1 * DD;
        const int dbase = ng * 64 + rr * 2;
#pragma unroll
        for (int nt = 0; nt < 8; nt++) {
            const int d = dbase + nt * 8;
            const float2 hv0 = *(const float2*)(h0 + d);
            const float mx0 = hv0.x * acc[nt][0], my0 = hv0.y * acc[nt][1];
            asm volatile("red.global.add.v2.f32 [%0], {%1,%2};"
                         :: "l"(a0p + d), "f"(mx0), "f"(my0) : "memory");
            const float2 hv1 = *(const float2*)(h1 + d);
            const float mx1 = hv1.x * acc[nt][2], my1 = hv1.y * acc[nt][3];
            asm volatile("red.global.add.v2.f32 [%0], {%1,%2};"
                         :: "l"(a1p + d), "f"(mx1), "f"(my1) : "memory");
        }

        // commit prefetched chunk to the other buffer (tf32-converted)
        if (c + 1 < ce) {
            float* dstb = as + (buf ^ 1) * ECH * A_STR;
            np = 0;
            for (int idx = t; idx < EVEC; idx += 256, np++) {
                const int f0 = idx * 4;
                const int e = f0 / FAB, col = f0 % FAB;
                float4 o;
                o.x = to_tf32(pre[np].x); o.y = to_tf32(pre[np].y);
                o.z = to_tf32(pre[np].z); o.w = to_tf32(pre[np].w);
                *(float4*)(dstb + e * A_STR + col) = o;
            }
        }
        __syncthreads();
        buf ^= 1;
    }
}

// ---------------- root GEMM: h2 = relu(h @ root_w + root_b + agg) -> g_agg ----------------
__global__ void __launch_bounds__(256, 1)
k_root(const float* __restrict__ W, const float* __restrict__ bias) {
    extern __shared__ float sm[];
    float* hs = sm;               // 32*256 floats
    float* ws = sm + 32 * 256;    // 64*256 floats
    const int t = threadIdx.x;
    const int row0 = blockIdx.x * 32;
    for (int idx = t; idx < 32 * 256; idx += 256)
        hs[idx] = g_h[(size_t)(row0 + (idx >> 8)) * DD + (idx & 255)];
    const int d0 = (t & 63) * 4, i0 = (t >> 6) * 8;
    float acc[8][4] = {};
    for (int kt = 0; kt < 4; kt++) {
        __syncthreads();
        for (int idx = t; idx < 64 * 256; idx += 256)
            ws[idx] = W[(size_t)(kt * 64 + (idx >> 8)) * DD + (idx & 255)];
        __syncthreads();
#pragma unroll 2
        for (int k = 0; k < 64; k++) {
            const float4 wv = *(const float4*)&ws[k * 256 + d0];
#pragma unroll
            for (int j = 0; j < 8; j++) {
                const float av = hs[(i0 + j) * 256 + kt * 64 + k];
                acc[j][0] += av * wv.x; acc[j][1] += av * wv.y;
                acc[j][2] += av * wv.z; acc[j][3] += av * wv.w;
            }
        }
    }
    const float4 bv = *(const float4*)&bias[d0];
#pragma unroll
    for (int j = 0; j < 8; j++) {
        const size_t base = (size_t)(row0 + i0 + j) * DD + d0;
        float4 ag = *(const float4*)&g_agg[base];
        float4 r;
        r.x = fmaxf(acc[j][0] + bv.x + ag.x, 0.0f);
        r.y = fmaxf(acc[j][1] + bv.y + ag.y, 0.0f);
        r.z = fmaxf(acc[j][2] + bv.z + ag.z, 0.0f);
        r.w = fmaxf(acc[j][3] + bv.w + ag.w, 0.0f);
        *(float4*)&g_agg[base] = r;
    }
}

// ---------------- LSTM gates GEMM: gates = q_star@Wih + hq@Whh + b ----------------
__global__ void k_lstm(const float* __restrict__ Wih, const float* __restrict__ Whh,
                       const float* __restrict__ bias) {
    extern __shared__ float sm[];
    float* aq = sm;                 // 16*512
    float* ah = sm + 8192;          // 16*256
    float* ws = sm + 12288;         // 64*256
    const int t = threadIdx.x;
    const int row0 = blockIdx.x * 16, col0 = blockIdx.y * 256;
    for (int idx = t; idx < 16 * 512; idx += 256)
        aq[idx] = g_q[(size_t)(row0 + (idx >> 9)) * 512 + (idx & 511)];
    for (int idx = t; idx < 16 * 256; idx += 256)
        ah[idx] = g_hq[(size_t)(row0 + (idx >> 8)) * 256 + (idx & 255)];
    const int d0 = (t & 63) * 4, i0 = (t >> 6) * 4;
    float acc[4][4] = {};
    for (int kt = 0; kt < 8; kt++) {  // Wih, K=512
        __syncthreads();
        for (int idx = t; idx < 64 * 256; idx += 256)
            ws[idx] = Wih[(size_t)(kt * 64 + (idx >> 8)) * 1024 + col0 + (idx & 255)];
        __syncthreads();
#pragma unroll
        for (int k = 0; k < 64; k++) {
            const float4 wv = *(const float4*)&ws[k * 256 + d0];
#pragma unroll
            for (int j = 0; j < 4; j++) {
                const float av = aq[(i0 + j) * 512 + kt * 64 + k];
                acc[j][0] += av * wv.x; acc[j][1] += av * wv.y;
                acc[j][2] += av * wv.z; acc[j][3] += av * wv.w;
            }
        }
    }
    for (int kt = 0; kt < 4; kt++) {  // Whh, K=256
        __syncthreads();
        for (int idx = t; idx < 64 * 256; idx += 256)
            ws[idx] = Whh[(size_t)(kt * 64 + (idx >> 8)) * 1024 + col0 + (idx & 255)];
        __syncthreads();
#pragma unroll
        for (int k = 0; k < 64; k++) {
            const float4 wv = *(const float4*)&ws[k * 256 + d0];
#pragma unroll
            for (int j = 0; j < 4; j++) {
                const float av = ah[(i0 + j) * 256 + kt * 64 + k];
                acc[j][0] += av * wv.x; acc[j][1] += av * wv.y;
                acc[j][2] += av * wv.z; acc[j][3] += av * wv.w;
            }
        }
    }
    const float4 bv = *(const float4*)&bias[col0 + d0];
#pragma unroll
    for (int j = 0; j < 4; j++) {
        float4 r;
        r.x = acc[j][0] + bv.x; r.y = acc[j][1] + bv.y;
        r.z = acc[j][2] + bv.z; r.w = acc[j][3] + bv.w;
        *(float4*)&g_gates[(size_t)(row0 + i0 + j) * 1024 + col0 + d0] = r;
    }
}

// ---------------- LSTM cell update ----------------
__global__ void k_cell(const float* __restrict__ bias, int useBias) {
    const int idx = blockIdx.x * blockDim.x + threadIdx.x;
    if (idx >= BBG * DD) return;
    const int b = idx >> 8, d = idx & 255;
    float gi, gf, gg, go;
    if (useBias) {  // step 0: q_star = hq = 0 algebraically => gates = bias
        gi = bias[d]; gf = bias[DD + d]; gg = bias[2 * DD + d]; go = bias[3 * DD + d];
    } else {
        const float* gp = g_gates + (size_t)b * 1024;
        gi = gp[d]; gf = gp[DD + d]; gg = gp[2 * DD + d]; go = gp[3 * DD + d];
    }
    const float c = sigf(gf) * g_c[idx] + sigf(gi) * tanhf(gg);
    g_c[idx] = c;
    const float hv = sigf(go) * tanhf(c);
    g_hq[idx] = hv;
    g_q[(size_t)b * 512 + d] = hv;
}

// ---------------- attention scores: e[n] = dot(h2[n], hq[batch[n]]) ----------------
__global__ void k_e(const void* __restrict__ batch) {
    const int t = threadIdx.x, wid = t >> 5, lane = t & 31;
    const int n = blockIdx.x * 8 + wid;
    if (n >= NN) return;
    const int is64 = g_is64;
    const int b = ld_idx(batch, n, is64);
    const float4* hp = (const float4*)(g_agg + (size_t)n * DD);
    const float4* qp = (const float4*)(g_hq + (size_t)b * DD);
    float s = 0.0f;
#pragma unroll
    for (int r = 0; r < 2; r++) {
        const float4 a = hp[lane + 32 * r];
        const float4 q = qp[lane + 32 * r];
        s += a.x * q.x + a.y * q.y + a.z * q.z + a.w * q.w;
    }
#pragma unroll
    for (int o = 16; o; o >>= 1) s += __shfl_xor_sync(0xffffffffu, s, o);
    if (lane == 0) g_e[n] = s;
}

// ---------------- segment softmax + weighted sum: r -> q_star[:,256:] ----------------
__global__ void k_attn() {  // one 128-thread block per graph; segments contiguous
    const int b = blockIdx.x, t = threadIdx.x;
    const int s0 = g_segstart[b], s1 = g_segstart[b + 1];
    __shared__ float sred[128];
    __shared__ float a_s[128];
    float lm = -3.4e38f;
    for (int n = s0 + t; n < s1; n += 128) lm = fmaxf(lm, g_e[n]);
    sred[t] = lm;
    __syncthreads();
    for (int o = 64; o > 0; o >>= 1) {
        if (t < o) sred[t] = fmaxf(sred[t], sred[t + o]);
        __syncthreads();
    }
    const float m = (s1 > s0) ? sred[0] : 0.0f;
    __syncthreads();
    float lz = 0.0f;
    for (int n = s0 + t; n < s1; n += 128) lz += __expf(g_e[n] - m);
    sred[t] = lz;
    __syncthreads();
    for (int o = 64; o > 0; o >>= 1) {
        if (t < o) sred[t] += sred[t + o];
        __syncthreads();
    }
    const float z = sred[0];
    __syncthreads();
    float rx = 0.0f, ry = 0.0f;
    for (int base = s0; base < s1; base += 128) {
        const int n = base + t;
        a_s[t] = (n < s1) ? __expf(g_e[n] - m) : 0.0f;
        __syncthreads();
        const int lim = min(128, s1 - base);
        for (int j = 0; j < lim; j++) {
            const float a = a_s[j];
            const float2 hv = *(const float2*)&g_agg[(size_t)(base + j) * DD + 2 * t];
            rx += a * hv.x;
            ry += a * hv.y;
        }
        __syncthreads();
    }
    const float inv = (s1 > s0) ? 1.0f / z : 0.0f;
    float2 out;
    out.x = rx * inv;
    out.y = ry * inv;
    *(float2*)&g_q[(size_t)b * 512 + 256 + 2 * t] = out;
}

// ---------------- head layer 1: hid = relu(q_star @ lin1_w + lin1_b) -> g_gates ----------------
__global__ void k_head1(const float* __restrict__ W, const float* __restrict__ bias) {
    extern __shared__ float sm[];
    float* aq = sm;             // 16*512
    float* ws = sm + 8192;      // 64*256
    const int t = threadIdx.x;
    const int row0 = blockIdx.x * 16;
    for (int idx = t; idx < 16 * 512; idx += 256)
        aq[idx] = g_q[(size_t)(row0 + (idx >> 9)) * 512 + (idx & 511)];
    const int d0 = (t & 63) * 4, i0 = (t >> 6) * 4;
    float acc[4][4] = {};
    for (int kt = 0; kt < 8; kt++) {
        __syncthreads();
        for (int idx = t; idx < 64 * 256; idx += 256)
            ws[idx] = W[(size_t)(kt * 64 + (idx >> 8)) * DD + (idx & 255)];
        __syncthreads();
#pragma unroll
        for (int k = 0; k < 64; k++) {
            const float4 wv = *(const float4*)&ws[k * 256 + d0];
#pragma unroll
            for (int j = 0; j < 4; j++) {
                const float av = aq[(i0 + j) * 512 + kt * 64 + k];
                acc[j][0] += av * wv.x; acc[j][1] += av * wv.y;
                acc[j][2] += av * wv.z; acc[j][3] += av * wv.w;
            }
        }
    }
    const float4 bv = *(const float4*)&bias[d0];
#pragma unroll
    for (int j = 0; j < 4; j++) {
        float4 r;
        r.x = fmaxf(acc[j][0] + bv.x, 0.0f);
        r.y = fmaxf(acc[j][1] + bv.y, 0.0f);
        r.z = fmaxf(acc[j][2] + bv.z, 0.0f);
        r.w = fmaxf(acc[j][3] + bv.w, 0.0f);
        *(float4*)&g_gates[(size_t)(row0 + i0 + j) * DD + d0] = r;
    }
}

// ---------------- head layer 2: out = hid @ lin2_w + lin2_b ----------------
__global__ void k_head2(const float* __restrict__ w2, const float* __restrict__ b2,
                        float* __restrict__ out) {
    const int t = threadIdx.x, wid = t >> 5, lane = t & 31;
    const int g = blockIdx.x * 8 + wid;
    if (g >= BBG) return;
    const float4* hp = (const float4*)(g_gates + (size_t)g * DD);
    const float4* wp = (const float4*)w2;
    float s = 0.0f;
#pragma unroll
    for (int r = 0; r < 2; r++) {
        const float4 a = hp[lane + 32 * r];
        const float4 w = wp[lane + 32 * r];
        s += a.x * w.x + a.y * w.y + a.z * w.z + a.w * w.w;
    }
#pragma unroll
    for (int o = 16; o; o >>= 1) s += __shfl_xor_sync(0xffffffffu, s, o);
    if (lane == 0) out[g] = s + b2[0];
}

// ---------------- host launch ----------------
extern "C" void kernel_launch(void* const* d_in, const int* in_sizes, int n_in,
                              void* d_out, int out_size) {
    const float* x      = (const float*)d_in[0];
    const void*  eidx   = d_in[1];
    const float* eattr  = (const float*)d_in[2];
    const void*  batch  = d_in[3];
    const float* lin0_w = (const float*)d_in[4];
    const float* lin0_b = (const float*)d_in[5];
    const float* root_w = (const float*)d_in[6];
    const float* root_b = (const float*)d_in[7];
    const float* nn_w   = (const float*)d_in[8];
    const float* nn_b   = (const float*)d_in[9];
    const float* wih    = (const float*)d_in[10];
    const float* whh    = (const float*)d_in[11];
    const float* lstm_b = (const float*)d_in[12];
    const float* lin1_w = (const float*)d_in[13];
    const float* lin1_b = (const float*)d_in[14];
    const float* lin2_w = (const float*)d_in[15];
    const float* lin2_b = (const float*)d_in[16];
    float* out = (float*)d_out;

    const int EDGE_SMEM = (KPAD * B_STR + 2 * ECH * A_STR) * 4;     // 137472
    const int ROOT_SMEM = (32 * 256 + 64 * 256) * 4;                // 98304
    const int LSTM_SMEM = (16 * 512 + 16 * 256 + 64 * 256) * 4;     // 114688
    const int HEAD_SMEM = (16 * 512 + 64 * 256) * 4;                // 98304
    cudaFuncSetAttribute(k_edge,  cudaFuncAttributeMaxDynamicSharedMemorySize, EDGE_SMEM);
    cudaFuncSetAttribute(k_root,  cudaFuncAttributeMaxDynamicSharedMemorySize, ROOT_SMEM);
    cudaFuncSetAttribute(k_lstm,  cudaFuncAttributeMaxDynamicSharedMemorySize, LSTM_SMEM);
    cudaFuncSetAttribute(k_head1, cudaFuncAttributeMaxDynamicSharedMemorySize, HEAD_SMEM);

    // launch order chosen so k_edge is launch index 3 (the one ncu captures)
    k_detect<<<1, 512>>>((const unsigned int*)eidx);
    k_lin0<<<NN / 16, 256>>>(x, lin0_w, lin0_b);
    k_zero_agg<<<4096, 256>>>();
    k_edge<<<148, 256, EDGE_SMEM>>>(eidx, eattr, nn_w, nn_b);   // idx 3
    k_zero_state<<<1024, 256>>>();
    k_hist<<<400, 256>>>(batch);
    k_scan<<<1, 1024>>>();
    k_root<<<NN / 32, 256, ROOT_SMEM>>>(root_w, root_b);

    for (int s = 0; s < 3; s++) {
        if (s == 0) {
            k_cell<<<BBG, 256>>>(lstm_b, 1);
        } else {
            k_lstm<<<dim3(BBG / 16, 4), 256, LSTM_SMEM>>>(wih, whh, lstm_b);
            k_cell<<<BBG, 256>>>(lstm_b, 0);
        }
        k_e<<<NN / 8, 256>>>(batch);
        k_attn<<<BBG, 128>>>();
    }

    k_head1<<<BBG / 16, 256, HEAD_SMEM>>>(lin1_w, lin1_b);
    k_head2<<<BBG / 8, 256>>>(lin2_w, lin2_b, out);
}

// round 5
// speedup vs baseline: 2.1542x; 1.3402x over previous
#include <cuda_runtime.h>
#include <math.h>
#include <stdint.h>

// Problem constants (fixed by the reference setup_inputs)
#define NN    100000
#define EE    400000
#define BBG   4096
#define DD    256
#define MOLIN 25
#define FAB   100

// ---------------- device scratch (no allocations allowed) ----------------
__device__ float g_h[(size_t)NN * DD];     // post-lin0 node features
__device__ float g_agg[(size_t)NN * DD];   // message aggregation; becomes h2 after root
__device__ float g_e[NN];                  // attention scores (fallback path only)
__device__ float g_hq[BBG * DD];           // LSTM hidden
__device__ float g_c[BBG * DD];            // LSTM cell
__device__ float g_q[BBG * 2 * DD];        // q_star = [hq, r]
__device__ float g_gates[BBG * 4 * DD];    // LSTM gates; reused as head hidden
__device__ float g_wcomb[512 * 1024];      // folded LSTM weights
__device__ int   g_counts[BBG];
__device__ int   g_segstart[BBG + 1];
__device__ int   g_is64;

__device__ __forceinline__ int ld_idx(const void* p, int i, int is64) {
    if (is64) return (int)((const long long*)p)[i];
    return ((const int*)p)[i];
}

__device__ __forceinline__ float sigf(float x) {
    return 1.0f / (1.0f + __expf(-x));
}

// tf32 conversion: destination must be a .b32 register for ptxas
__device__ __forceinline__ float to_tf32(float v) {
    uint32_t o;
    asm("cvt.rna.tf32.f32 %0, %1;" : "=r"(o) : "f"(v));
    return __uint_as_float(o);
}

// ---------------- dtype detection: int64 vs int32 indices ----------------
__global__ void k_detect(const unsigned int* words) {
    __shared__ int nz;
    if (threadIdx.x == 0) nz = 0;
    __syncthreads();
    unsigned v = words[2 * threadIdx.x + 1];
    if (v) atomicOr(&nz, 1);
    __syncthreads();
    if (threadIdx.x == 0) g_is64 = nz ? 0 : 1;
}

// ---------------- zero kernels ----------------
__global__ void k_zero_agg() {
    const int n = NN * DD;
    for (int i = blockIdx.x * blockDim.x + threadIdx.x; i < n; i += gridDim.x * blockDim.x)
        g_agg[i] = 0.0f;
}
__global__ void k_zero_state() {
    const int n = BBG * DD;
    for (int i = blockIdx.x * blockDim.x + threadIdx.x; i < n; i += gridDim.x * blockDim.x) {
        g_c[i] = 0.0f;
        if (i < BBG) g_counts[i] = 0;
    }
}

// ---------------- Wcomb = [Wih_top + Whh ; Wih_bot] ----------------
__global__ void k_wcomb(const float* __restrict__ wih, const float* __restrict__ whh) {
    const int i = blockIdx.x * 256 + threadIdx.x;
    if (i >= 512 * 1024) return;
    const int k = i >> 10, j = i & 1023;
    float v = wih[i];
    if (k < 256) v += whh[k * 1024 + j];
    g_wcomb[i] = v;
}

// ---------------- lin0: h = relu(x @ W0 + b0) ----------------
__global__ void k_lin0(const float* __restrict__ x, const float* __restrict__ W,
                       const float* __restrict__ b) {
    __shared__ float xs[16 * MOLIN];
    const int t = threadIdx.x;
    const int row0 = blockIdx.x * 16;
    for (int idx = t; idx < 16 * MOLIN; idx += 256)
        xs[idx] = x[row0 * MOLIN + idx];
    float w[MOLIN];
#pragma unroll
    for (int k = 0; k < MOLIN; k++) w[k] = W[k * DD + t];
    const float bd = b[t];
    __syncthreads();
#pragma unroll 4
    for (int i = 0; i < 16; i++) {
        float acc = bd;
#pragma unroll
        for (int k = 0; k < MOLIN; k++) acc += xs[i * MOLIN + k] * w[k];
        g_h[(size_t)(row0 + i) * DD + t] = fmaxf(acc, 0.0f);
    }
}

// ---------------- segment boundaries (batch is sorted) ----------------
__global__ void k_hist(const void* __restrict__ batch) {
    const int is64 = g_is64;
    for (int n = blockIdx.x * blockDim.x + threadIdx.x; n < NN; n += gridDim.x * blockDim.x) {
        int b = ld_idx(batch, n, is64);
        atomicAdd(&g_counts[b], 1);
    }
}

__global__ void k_scan() {  // 1 block, 1024 threads; exclusive scan of 4096 counts
    const int t = threadIdx.x;
    int c[4];
#pragma unroll
    for (int j = 0; j < 4; j++) c[j] = g_counts[t * 4 + j];
    int s = c[0] + c[1] + c[2] + c[3];
    const int lane = t & 31, wid = t >> 5;
    int inc = s;
#pragma unroll
    for (int o = 1; o < 32; o <<= 1) {
        int v = __shfl_up_sync(0xffffffffu, inc, o);
        if (lane >= o) inc += v;
    }
    __shared__ int wex[32];
    if (lane == 31) wex[wid] = inc;
    __syncthreads();
    if (wid == 0) {
        int v = wex[lane];
        int wi = v;
#pragma unroll
        for (int o = 1; o < 32; o <<= 1) {
            int u = __shfl_up_sync(0xffffffffu, wi, o);
            if (lane >= o) wi += u;
        }
        wex[lane] = wi - v;  // exclusive
    }
    __syncthreads();
    int run = wex[wid] + (inc - s);
#pragma unroll
    for (int j = 0; j < 4; j++) {
        g_segstart[t * 4 + j] = run;
        run += c[j];
    }
    if (t == 1023) g_segstart[BBG] = run;
}

// ---------------- fused edge kernel: tf32 mma.sync, 512 threads ----------------
// ew = [eattr | 1] @ [nn_w ; nn_b]; msg = h[src]*ew; agg[dst] += msg
// 16 warps: 4 edge-groups x 4 dim-groups; warp tile 16 edges x 64 dims.
#define ECH   64
#define EVEC  (ECH * FAB / 4)   // 1600 float4 per chunk
#define KPAD  104
#define A_STR 108
#define B_STR 264
__global__ void __launch_bounds__(512, 1)
k_edge(const void* __restrict__ eidx, const float* __restrict__ eattr,
       const float* __restrict__ nnw, const float* __restrict__ nnb) {
    extern __shared__ float sm[];
    float* ws = sm;                      // KPAD * B_STR = 27456 floats
    float* as = ws + KPAD * B_STR;       // 2 * ECH * A_STR = 13824 floats
    const int t = threadIdx.x;
    const int is64 = g_is64;

    // weights (+bias row 100, zero rows 101-103), tf32-converted
    for (int idx = t; idx < KPAD * 256; idx += 512) {
        const int r = idx >> 8, cc = idx & 255;
        float v = (r < FAB) ? nnw[r * 256 + cc] : (r == FAB ? nnb[cc] : 0.0f);
        ws[r * B_STR + cc] = to_tf32(v);
    }
    // attr pad columns (both buffers): col 100 = 1.0 (bias), 101..107 = 0
    for (int idx = t; idx < 2 * ECH; idx += 512) {
        float* row = as + idx * A_STR;
#pragma unroll
        for (int j = 100; j < 108; j++) row[j] = 0.0f;
        row[100] = 1.0f;
    }

    const int NCH = EE / ECH;            // 6250
    const int per = (NCH + gridDim.x - 1) / gridDim.x;
    const int cs = blockIdx.x * per;
    const int ce = min(NCH, cs + per);
    if (cs >= ce) return;

    const float4* ea = (const float4*)eattr;
    // preload first chunk into buffer 0
    for (int idx = t; idx < EVEC; idx += 512) {
        float4 v = ea[(size_t)cs * EVEC + idx];
        const int f0 = idx * 4;
        const int e = f0 / FAB, col = f0 % FAB;
        float4 o;
        o.x = to_tf32(v.x); o.y = to_tf32(v.y);
        o.z = to_tf32(v.z); o.w = to_tf32(v.w);
        *(float4*)(as + e * A_STR + col) = o;
    }
    __syncthreads();

    const int w = t >> 5, lane = t & 31;
    const int eg = w >> 2, ng = w & 3;       // edge group (0..3), dim group (0..3)
    const int qr = lane >> 2, rr = lane & 3; // quad-row, quad-col

    int buf = 0;
    for (int c = cs; c < ce; ++c) {
        // prefetch next chunk (raw) into registers
        float4 pre[4];
        int np = 0;
        if (c + 1 < ce) {
            for (int idx = t; idx < EVEC; idx += 512, np++)
                pre[np] = ea[(size_t)(c + 1) * EVEC + idx];
        }

        // ---- MMA: C[16 edges x 64 dims] per warp ----
        float acc[8][4];
#pragma unroll
        for (int nt = 0; nt < 8; nt++)
#pragma unroll
            for (int j = 0; j < 4; j++) acc[nt][j] = 0.0f;

        const float* A = as + buf * ECH * A_STR + (eg * 16 + qr) * A_STR;
#pragma unroll
        for (int ks = 0; ks < 13; ks++) {
            const int k0 = ks * 8;
            const uint32_t a0 = __float_as_uint(A[k0 + rr]);
            const uint32_t a1 = __float_as_uint(A[8 * A_STR + k0 + rr]);
            const uint32_t a2 = __float_as_uint(A[k0 + rr + 4]);
            const uint32_t a3 = __float_as_uint(A[8 * A_STR + k0 + rr + 4]);
            const float* Bp = ws + (k0 + rr) * B_STR + ng * 64 + qr;
#pragma unroll
            for (int nt = 0; nt < 8; nt++) {
                const uint32_t b0 = __float_as_uint(Bp[nt * 8]);
                const uint32_t b1 = __float_as_uint(Bp[4 * B_STR + nt * 8]);
                asm volatile(
                    "mma.sync.aligned.m16n8k8.row.col.f32.tf32.tf32.f32 "
                    "{%0,%1,%2,%3}, {%4,%5,%6,%7}, {%8,%9}, {%0,%1,%2,%3};"
                    : "+f"(acc[nt][0]), "+f"(acc[nt][1]),
                      "+f"(acc[nt][2]), "+f"(acc[nt][3])
                    : "r"(a0), "r"(a1), "r"(a2), "r"(a3), "r"(b0), "r"(b1));
            }
        }

        // ---- epilogue: gather h[src], modulate, scatter to agg[dst] ----
        const int ebase = c * ECH + eg * 16;
        const int e0 = ebase + qr, e1 = ebase + qr + 8;
        const int s0 = ld_idx(eidx, e0, is64), d0 = ld_idx(eidx, EE + e0, is64);
        const int s1 = ld_idx(eidx, e1, is64), d1 = ld_idx(eidx, EE + e1, is64);
        const float* h0 = g_h + (size_t)s0 * DD;
        const float* h1 = g_h + (size_t)s1 * DD;
        float* a0p = g_agg + (size_t)d0 * DD;
        float* a1p = g_agg + (size_t)d1 * DD;
        const int dbase = ng * 64 + rr * 2;
#pragma unroll
        for (int nt = 0; nt < 8; nt++) {
            const int d = dbase + nt * 8;
            const float2 hv0 = *(const float2*)(h0 + d);
            const float mx0 = hv0.x * acc[nt][0], my0 = hv0.y * acc[nt][1];
            asm volatile("red.global.add.v2.f32 [%0], {%1,%2};"
                         :: "l"(a0p + d), "f"(mx0), "f"(my0) : "memory");
            const float2 hv1 = *(const float2*)(h1 + d);
            const float mx1 = hv1.x * acc[nt][2], my1 = hv1.y * acc[nt][3];
            asm volatile("red.global.add.v2.f32 [%0], {%1,%2};"
                         :: "l"(a1p + d), "f"(mx1), "f"(my1) : "memory");
        }

        // commit prefetched chunk to the other buffer (tf32-converted)
        if (c + 1 < ce) {
            float* dstb = as + (buf ^ 1) * ECH * A_STR;
            np = 0;
            for (int idx = t; idx < EVEC; idx += 512, np++) {
                const int f0 = idx * 4;
                const int e = f0 / FAB, col = f0 % FAB;
                float4 o;
                o.x = to_tf32(pre[np].x); o.y = to_tf32(pre[np].y);
                o.z = to_tf32(pre[np].z); o.w = to_tf32(pre[np].w);
                *(float4*)(dstb + e * A_STR + col) = o;
            }
        }
        __syncthreads();
        buf ^= 1;
    }
}

// ---------------- root GEMM (tf32 mma): h2 = relu(h @ root_w + root_b + agg) ----------------
// Block tile 64x256, K=256. A (h rows) resident in smem; W in 64-row k-slices.
#define R_ASTR 268   // mod 32 == 12 -> bank-bijective A frags
#define R_BSTR 264   // mod 32 == 8  -> bank-bijective B frags
__global__ void __launch_bounds__(256, 1)
k_root(const float* __restrict__ W, const float* __restrict__ bias) {
    extern __shared__ float sm[];
    float* as2 = sm;                   // 64 * R_ASTR
    float* ws2 = sm + 64 * R_ASTR;     // 64 * R_BSTR
    const int t = threadIdx.x;
    const int row0 = blockIdx.x * 64;

    for (int idx = t; idx < 64 * 256; idx += 256) {
        const int r = idx >> 8, c2 = idx & 255;
        const int gr = row0 + r;
        float v = (gr < NN) ? g_h[(size_t)gr * DD + c2] : 0.0f;
        as2[r * R_ASTR + c2] = to_tf32(v);
    }

    const int w = t >> 5, lane = t & 31;
    const int wm = w >> 2, wn = w & 3;       // warp: 2 m-groups x 4 n-groups
    const int qr = lane >> 2, rr = lane & 3;

    float acc[2][8][4];
#pragma unroll
    for (int mt = 0; mt < 2; mt++)
#pragma unroll
        for (int nt = 0; nt < 8; nt++)
#pragma unroll
            for (int j = 0; j < 4; j++) acc[mt][nt][j] = 0.0f;

    for (int kt = 0; kt < 4; kt++) {
        __syncthreads();
        for (int idx = t; idx < 64 * 256; idx += 256) {
            const int r = idx >> 8, c2 = idx & 255;
            ws2[r * R_BSTR + c2] = to_tf32(W[(size_t)(kt * 64 + r) * DD + c2]);
        }
        __syncthreads();
#pragma unroll
        for (int ks = 0; ks < 8; ks++) {
            const int kg = kt * 64 + ks * 8;   // global k (A is full-K)
            const int kl = ks * 8;             // local k (B slice)
            uint32_t a[2][4];
#pragma unroll
            for (int mt = 0; mt < 2; mt++) {
                const int rA = wm * 32 + mt * 16;
                a[mt][0] = __float_as_uint(as2[(rA + qr) * R_ASTR + kg + rr]);
                a[mt][1] = __float_as_uint(as2[(rA + qr + 8) * R_ASTR + kg + rr]);
                a[mt][2] = __float_as_uint(as2[(rA + qr) * R_ASTR + kg + rr + 4]);
                a[mt][3] = __float_as_uint(as2[(rA + qr + 8) * R_ASTR + kg + rr + 4]);
            }
            const float* Bp = ws2 + (kl + rr) * R_BSTR + wn * 64 + qr;
#pragma unroll
            for (int nt = 0; nt < 8; nt++) {
                const uint32_t b0 = __float_as_uint(Bp[nt * 8]);
                const uint32_t b1 = __float_as_uint(Bp[4 * R_BSTR + nt * 8]);
#pragma unroll
                for (int mt = 0; mt < 2; mt++) {
                    asm volatile(
                        "mma.sync.aligned.m16n8k8.row.col.f32.tf32.tf32.f32 "
                        "{%0,%1,%2,%3}, {%4,%5,%6,%7}, {%8,%9}, {%0,%1,%2,%3};"
                        : "+f"(acc[mt][nt][0]), "+f"(acc[mt][nt][1]),
                          "+f"(acc[mt][nt][2]), "+f"(acc[mt][nt][3])
                        : "r"(a[mt][0]), "r"(a[mt][1]), "r"(a[mt][2]), "r"(a[mt][3]),
                          "r"(b0), "r"(b1));
                }
            }
        }
    }

#pragma unroll
    for (int mt = 0; mt < 2; mt++) {
        const int r0 = row0 + wm * 32 + mt * 16 + qr;
        const int r1 = r0 + 8;
#pragma unroll
        for (int nt = 0; nt < 8; nt++) {
            const int col = wn * 64 + nt * 8 + rr * 2;
            const float bx = bias[col], by = bias[col + 1];
            if (r0 < NN) {
                float2 ag = *(const float2*)&g_agg[(size_t)r0 * DD + col];
                float2 o;
                o.x = fmaxf(acc[mt][nt][0] + bx + ag.x, 0.0f);
                o.y = fmaxf(acc[mt][nt][1] + by + ag.y, 0.0f);
                *(float2*)&g_agg[(size_t)r0 * DD + col] = o;
            }
            if (r1 < NN) {
                float2 ag = *(const float2*)&g_agg[(size_t)r1 * DD + col];
                float2 o;
                o.x = fmaxf(acc[mt][nt][2] + bx + ag.x, 0.0f);
                o.y = fmaxf(acc[mt][nt][3] + by + ag.y, 0.0f);
                *(float2*)&g_agg[(size_t)r1 * DD + col] = o;
            }
        }
    }
}

// ---------------- LSTM gates GEMM (folded): gates = q_star @ Wcomb + b ----------------
__global__ void k_lstm2(const float* __restrict__ bias) {
    extern __shared__ float sm[];
    float* aq = sm;                 // 16*512
    float* ws = sm + 8192;          // 64*256
    const int t = threadIdx.x;
    const int row0 = blockIdx.x * 16, col0 = blockIdx.y * 256;
    for (int idx = t; idx < 16 * 512; idx += 256)
        aq[idx] = g_q[(size_t)(row0 + (idx >> 9)) * 512 + (idx & 511)];
    const int d0 = (t & 63) * 4, i0 = (t >> 6) * 4;
    float acc[4][4] = {};
    for (int kt = 0; kt < 8; kt++) {  // K=512
        __syncthreads();
        for (int idx = t; idx < 64 * 256; idx += 256)
            ws[idx] = g_wcomb[(size_t)(kt * 64 + (idx >> 8)) * 1024 + col0 + (idx & 255)];
        __syncthreads();
#pragma unroll
        for (int k = 0; k < 64; k++) {
            const float4 wv = *(const float4*)&ws[k * 256 + d0];
#pragma unroll
            for (int j = 0; j < 4; j++) {
                const float av = aq[(i0 + j) * 512 + kt * 64 + k];
                acc[j][0] += av * wv.x; acc[j][1] += av * wv.y;
                acc[j][2] += av * wv.z; acc[j][3] += av * wv.w;
            }
        }
    }
    const float4 bv = *(const float4*)&bias[col0 + d0];
#pragma unroll
    for (int j = 0; j < 4; j++) {
        float4 r;
        r.x = acc[j][0] + bv.x; r.y = acc[j][1] + bv.y;
        r.z = acc[j][2] + bv.z; r.w = acc[j][3] + bv.w;
        *(float4*)&g_gates[(size_t)(row0 + i0 + j) * 1024 + col0 + d0] = r;
    }
}

// ---------------- LSTM cell update ----------------
__global__ void k_cell(const float* __restrict__ bias, int useBias) {
    const int idx = blockIdx.x * blockDim.x + threadIdx.x;
    if (idx >= BBG * DD) return;
    const int b = idx >> 8, d = idx & 255;
    float gi, gf, gg, go;
    if (useBias) {  // step 0: q_star = hq = 0 algebraically => gates = bias
        gi = bias[d]; gf = bias[DD + d]; gg = bias[2 * DD + d]; go = bias[3 * DD + d];
    } else {
        const float* gp = g_gates + (size_t)b * 1024;
        gi = gp[d]; gf = gp[DD + d]; gg = gp[2 * DD + d]; go = gp[3 * DD + d];
    }
    const float c = sigf(gf) * g_c[idx] + sigf(gi) * tanhf(gg);
    g_c[idx] = c;
    const float hv = sigf(go) * tanhf(c);
    g_hq[idx] = hv;
    g_q[(size_t)b * 512 + d] = hv;
}

// ---------------- fused attention: scores + segment softmax + weighted sum ----------------
// One 256-thread block per graph. Segment cached in smem (CAP rows); rare
// oversize segments fall back to streaming via g_e.
#define CAP 96
__global__ void k_attn2() {
    extern __shared__ float smf[];
    float* hqv = smf;                  // 256
    float* es  = smf + 256;            // CAP (cached path) / 256 chunk (fallback)
    float* red = smf + 256 + 256;      // 32
    float* hs  = smf + 256 + 256 + 32; // CAP*256
    const int b = blockIdx.x, t = threadIdx.x;
    const int w = t >> 5, lane = t & 31;
    const int s0 = g_segstart[b], s1 = g_segstart[b + 1];
    const int len = s1 - s0;

    hqv[t] = g_hq[(size_t)b * DD + t];
    __syncthreads();

    if (len == 0) {
        g_q[(size_t)b * 512 + 256 + t] = 0.0f;
        return;
    }

    if (len <= CAP) {
        // cache segment rows
        const float4* src = (const float4*)(g_agg + (size_t)s0 * DD);
        float4* dst = (float4*)hs;
        for (int i = t; i < len * 64; i += 256) dst[i] = src[i];
        __syncthreads();
        // scores: one warp per node
        for (int i = w; i < len; i += 8) {
            const float4* hp = (const float4*)(hs + i * 256);
            const float4* qp = (const float4*)hqv;
            float s = 0.0f;
#pragma unroll
            for (int r2 = 0; r2 < 2; r2++) {
                const float4 a = hp[lane + 32 * r2];
                const float4 q = qp[lane + 32 * r2];
                s += a.x * q.x + a.y * q.y + a.z * q.z + a.w * q.w;
            }
#pragma unroll
            for (int o = 16; o; o >>= 1) s += __shfl_xor_sync(0xffffffffu, s, o);
            if (lane == 0) es[i] = s;
        }
        __syncthreads();
        // max
        float lm = -3.4e38f;
        for (int i = t; i < len; i += 256) lm = fmaxf(lm, es[i]);
#pragma unroll
        for (int o = 16; o; o >>= 1) lm = fmaxf(lm, __shfl_xor_sync(0xffffffffu, lm, o));
        if (lane == 0) red[w] = lm;
        __syncthreads();
        if (t == 0) {
            float mm = red[0];
#pragma unroll
            for (int j = 1; j < 8; j++) mm = fmaxf(mm, red[j]);
            red[16] = mm;
        }
        __syncthreads();
        const float m = red[16];
        // exp + sum (each es[i] touched by exactly one thread: len <= CAP < 256)
        float lz = 0.0f;
        for (int i = t; i < len; i += 256) {
            const float a = __expf(es[i] - m);
            es[i] = a;
            lz += a;
        }
#pragma unroll
        for (int o = 16; o; o >>= 1) lz += __shfl_xor_sync(0xffffffffu, lz, o);
        if (lane == 0) red[w] = lz;
        __syncthreads();
        if (t == 0) {
            float zz = red[0];
#pragma unroll
            for (int j = 1; j < 8; j++) zz += red[j];
            red[17] = zz;
        }
        __syncthreads();
        const float inv = 1.0f / red[17];
        // weighted sum: thread t owns dim t
        float r = 0.0f;
        for (int i = 0; i < len; i++) r += es[i] * hs[i * 256 + t];
        g_q[(size_t)b * 512 + 256 + t] = r * inv;
    } else {
        // fallback: compute e into g_e, then stream
        for (int i = s0 + w; i < s1; i += 8) {
            const float4* hp = (const float4*)(g_agg + (size_t)i * DD);
            const float4* qp = (const float4*)hqv;
            float s = 0.0f;
#pragma unroll
            for (int r2 = 0; r2 < 2; r2++) {
                const float4 a = hp[lane + 32 * r2];
                const float4 q = qp[lane + 32 * r2];
                s += a.x * q.x + a.y * q.y + a.z * q.z + a.w * q.w;
            }
#pragma unroll
            for (int o = 16; o; o >>= 1) s += __shfl_xor_sync(0xffffffffu, s, o);
            if (lane == 0) g_e[i] = s;
        }
        __syncthreads();
        float lm = -3.4e38f;
        for (int n = s0 + t; n < s1; n += 256) lm = fmaxf(lm, g_e[n]);
#pragma unroll
        for (int o = 16; o; o >>= 1) lm = fmaxf(lm, __shfl_xor_sync(0xffffffffu, lm, o));
        if (lane == 0) red[w] = lm;
        __syncthreads();
        if (t == 0) {
            float mm = red[0];
#pragma unroll
            for (int j = 1; j < 8; j++) mm = fmaxf(mm, red[j]);
            red[16] = mm;
        }
        __syncthreads();
        const float m = red[16];
        float lz = 0.0f;
        for (int n = s0 + t; n < s1; n += 256) lz += __expf(g_e[n] - m);
#pragma unroll
        for (int o = 16; o; o >>= 1) lz += __shfl_xor_sync(0xffffffffu, lz, o);
        if (lane == 0) red[w] = lz;
        __syncthreads();
        if (t == 0) {
            float zz = red[0];
#pragma unroll
            for (int j = 1; j < 8; j++) zz += red[j];
            red[17] = zz;
        }
        __syncthreads();
        const float inv = 1.0f / red[17];
        float r = 0.0f;
        for (int base = s0; base < s1; base += 256) {
            const int n = base + t;
            es[t] = (n < s1) ? __expf(g_e[n] - m) : 0.0f;  // es has 256 slots
            __syncthreads();
            const int lim = min(256, s1 - base);
            for (int j = 0; j < lim; j++)
                r += es[j] * g_agg[(size_t)(base + j) * DD + t];
            __syncthreads();
        }
        g_q[(size_t)b * 512 + 256 + t] = r * inv;
    }
}

// ---------------- head layer 1: hid = relu(q_star @ lin1_w + lin1_b) -> g_gates ----------------
__global__ void k_head1(const float* __restrict__ W, const float* __restrict__ bias) {
    extern __shared__ float sm[];
    float* aq = sm;             // 16*512
    float* ws = sm + 8192;      // 64*256
    const int t = threadIdx.x;
    const int row0 = blockIdx.x * 16;
    for (int idx = t; idx < 16 * 512; idx += 256)
        aq[idx] = g_q[(size_t)(row0 + (idx >> 9)) * 512 + (idx & 511)];
    const int d0 = (t & 63) * 4, i0 = (t >> 6) * 4;
    float acc[4][4] = {};
    for (int kt = 0; kt < 8; kt++) {
        __syncthreads();
        for (int idx = t; idx < 64 * 256; idx += 256)
            ws[idx] = W[(size_t)(kt * 64 + (idx >> 8)) * DD + (idx & 255)];
        __syncthreads();
#pragma unroll
        for (int k = 0; k < 64; k++) {
            const float4 wv = *(const float4*)&ws[k * 256 + d0];
#pragma unroll
            for (int j = 0; j < 4; j++) {
                const float av = aq[(i0 + j) * 512 + kt * 64 + k];
                acc[j][0] += av * wv.x; acc[j][1] += av * wv.y;
                acc[j][2] += av * wv.z; acc[j][3] += av * wv.w;
            }
        }
    }
    const float4 bv = *(const float4*)&bias[d0];
#pragma unroll
    for (int j = 0; j < 4; j++) {
        float4 r;
        r.x = fmaxf(acc[j][0] + bv.x, 0.0f);
        r.y = fmaxf(acc[j][1] + bv.y, 0.0f);
        r.z = fmaxf(acc[j][2] + bv.z, 0.0f);
        r.w = fmaxf(acc[j][3] + bv.w, 0.0f);
        *(float4*)&g_gates[(size_t)(row0 + i0 + j) * DD + d0] = r;
    }
}

// ---------------- head layer 2: out = hid @ lin2_w + lin2_b ----------------
__global__ void k_head2(const float* __restrict__ w2, const float* __restrict__ b2,
                        float* __restrict__ out) {
    const int t = threadIdx.x, wid = t >> 5, lane = t & 31;
    const int g = blockIdx.x * 8 + wid;
    if (g >= BBG) return;
    const float4* hp = (const float4*)(g_gates + (size_t)g * DD);
    const float4* wp = (const float4*)w2;
    float s = 0.0f;
#pragma unroll
    for (int r = 0; r < 2; r++) {
        const float4 a = hp[lane + 32 * r];
        const float4 w = wp[lane + 32 * r];
        s += a.x * w.x + a.y * w.y + a.z * w.z + a.w * w.w;
    }
#pragma unroll
    for (int o = 16; o; o >>= 1) s += __shfl_xor_sync(0xffffffffu, s, o);
    if (lane == 0) out[g] = s + b2[0];
}

// ---------------- host launch ----------------
extern "C" void kernel_launch(void* const* d_in, const int* in_sizes, int n_in,
                              void* d_out, int out_size) {
    const float* x      = (const float*)d_in[0];
    const void*  eidx   = d_in[1];
    const float* eattr  = (const float*)d_in[2];
    const void*  batch  = d_in[3];
    const float* lin0_w = (const float*)d_in[4];
    const float* lin0_b = (const float*)d_in[5];
    const float* root_w = (const float*)d_in[6];
    const float* root_b = (const float*)d_in[7];
    const float* nn_w   = (const float*)d_in[8];
    const float* nn_b   = (const float*)d_in[9];
    const float* wih    = (const float*)d_in[10];
    const float* whh    = (const float*)d_in[11];
    const float* lstm_b = (const float*)d_in[12];
    const float* lin1_w = (const float*)d_in[13];
    const float* lin1_b = (const float*)d_in[14];
    const float* lin2_w = (const float*)d_in[15];
    const float* lin2_b = (const float*)d_in[16];
    float* out = (float*)d_out;

    const int EDGE_SMEM = (KPAD * B_STR + 2 * ECH * A_STR) * 4;     // 165120
    const int ROOT_SMEM = (64 * R_ASTR + 64 * R_BSTR) * 4;          // 136192
    const int LSTM_SMEM = (16 * 512 + 64 * 256) * 4;                // 98304
    const int HEAD_SMEM = (16 * 512 + 64 * 256) * 4;                // 98304
    const int ATTN_SMEM = (256 + 256 + 32 + CAP * 256) * 4;         // 100480
    cudaFuncSetAttribute(k_edge,  cudaFuncAttributeMaxDynamicSharedMemorySize, EDGE_SMEM);
    cudaFuncSetAttribute(k_root,  cudaFuncAttributeMaxDynamicSharedMemorySize, ROOT_SMEM);
    cudaFuncSetAttribute(k_lstm2, cudaFuncAttributeMaxDynamicSharedMemorySize, LSTM_SMEM);
    cudaFuncSetAttribute(k_head1, cudaFuncAttributeMaxDynamicSharedMemorySize, HEAD_SMEM);
    cudaFuncSetAttribute(k_attn2, cudaFuncAttributeMaxDynamicSharedMemorySize, ATTN_SMEM);

    // launch order chosen so k_edge is launch index 3 (the one ncu captures)
    k_detect<<<1, 512>>>((const unsigned int*)eidx);
    k_lin0<<<NN / 16, 256>>>(x, lin0_w, lin0_b);
    k_zero_agg<<<4096, 256>>>();
    k_edge<<<148, 512, EDGE_SMEM>>>(eidx, eattr, nn_w, nn_b);   // idx 3
    k_zero_state<<<1024, 256>>>();
    k_hist<<<400, 256>>>(batch);
    k_scan<<<1, 1024>>>();
    k_wcomb<<<2048, 256>>>(wih, whh);
    k_root<<<(NN + 63) / 64, 256, ROOT_SMEM>>>(root_w, root_b);

    for (int s = 0; s < 3; s++) {
        if (s == 0) {
            k_cell<<<BBG, 256>>>(lstm_b, 1);
        } else {
            k_lstm2<<<dim3(BBG / 16, 4), 256, LSTM_SMEM>>>(lstm_b);
            k_cell<<<BBG, 256>>>(lstm_b, 0);
        }
        k_attn2<<<BBG, 256, ATTN_SMEM>>>();
    }

    k_head1<<<BBG / 16, 256, HEAD_SMEM>>>(lin1_w, lin1_b);
    k_head2<<<BBG / 8, 256>>>(lin2_w, lin2_b, out);
}